// round 8
// baseline (speedup 1.0000x reference)
#include <cuda_runtime.h>
#include <cuda_bf16.h>
#include <cstdint>
#include <cstddef>

#define NB   2
#define NN   3072
#define CC   512
#define MM   (NB * NN)      // 6144
#define HH   8
#define DD   64
#define KK   1536           // split-K: A=[hi|lo|hi], B=[hi|hi|lo]
#define NQKV 1536

// ---------------------------------------------------------------------------
// Device scratch
// ---------------------------------------------------------------------------
__device__ __align__(1024) __nv_bfloat16 g_A[(size_t)MM * KK];      // split activations
__device__ __align__(1024) __nv_bfloat16 g_Bqkv[(size_t)NQKV * KK]; // [Wq;Wk;Wv] split
__device__ __align__(1024) __nv_bfloat16 g_Bout[(size_t)CC * KK];   // Wp split
__device__ __align__(16)   float g_qkv[(size_t)MM * NQKV];          // q|k|v fp32

// ---------------------------------------------------------------------------
// helpers
// ---------------------------------------------------------------------------
__device__ __forceinline__ uint32_t smem_u32(const void* p) {
    uint32_t a;
    asm("{ .reg .u64 t; cvta.to.shared.u64 t, %1; cvt.u32.u64 %0, t; }" : "=r"(a) : "l"(p));
    return a;
}

#define CP16(dst_u32, src_ptr) \
    asm volatile("cp.async.cg.shared.global [%0], [%1], 16;" :: "r"(dst_u32), "l"(src_ptr))
#define CP_COMMIT()  asm volatile("cp.async.commit_group;" ::: "memory")
#define CP_WAITG(n)  asm volatile("cp.async.wait_group %0;" :: "n"(n) : "memory")

#define LDSM_X4(r0, r1, r2, r3, addr) \
    asm volatile("ldmatrix.sync.aligned.m8n8.x4.shared.b16 {%0,%1,%2,%3}, [%4];" \
                 : "=r"(r0), "=r"(r1), "=r"(r2), "=r"(r3) : "r"(addr))

__device__ __forceinline__ void mma16816(float* c, const uint32_t* a, const uint32_t* b) {
    asm volatile(
        "mma.sync.aligned.m16n8k16.row.col.f32.bf16.bf16.f32 "
        "{%0,%1,%2,%3}, {%4,%5,%6,%7}, {%8,%9}, {%0,%1,%2,%3};"
        : "+f"(c[0]), "+f"(c[1]), "+f"(c[2]), "+f"(c[3])
        : "r"(a[0]), "r"(a[1]), "r"(a[2]), "r"(a[3]), "r"(b[0]), "r"(b[1]));
}

// ---------------------------------------------------------------------------
// Hi/lo splitters:  activations -> [hi|lo|hi], weights -> [hi|hi|lo]
// Product: xhi*Whi + xlo*Whi + xhi*Wlo   (drops xlo*Wlo ~2^-18)
// ---------------------------------------------------------------------------
__device__ __forceinline__ void split_core(const float* __restrict__ in, int idx,
                                           int& r, int& c, uint2& H, uint2& L)
{
    r = idx >> 7;
    c = (idx & 127) << 2;
    float4 v = *reinterpret_cast<const float4*>(in + (size_t)r * CC + c);
    float f[4] = {v.x, v.y, v.z, v.w};
    uint32_t h[2], l[2];
    #pragma unroll
    for (int i = 0; i < 2; i++) {
        __nv_bfloat16 h0 = __float2bfloat16(f[2*i]);
        __nv_bfloat16 h1 = __float2bfloat16(f[2*i + 1]);
        __nv_bfloat16 l0 = __float2bfloat16(f[2*i]     - __bfloat162float(h0));
        __nv_bfloat16 l1 = __float2bfloat16(f[2*i + 1] - __bfloat162float(h1));
        h[i] = (uint32_t)__bfloat16_as_ushort(h0) | ((uint32_t)__bfloat16_as_ushort(h1) << 16);
        l[i] = (uint32_t)__bfloat16_as_ushort(l0) | ((uint32_t)__bfloat16_as_ushort(l1) << 16);
    }
    H = make_uint2(h[0], h[1]);
    L = make_uint2(l[0], l[1]);
}

__global__ void split3_a(const float* __restrict__ in, __nv_bfloat16* __restrict__ out, int rows)
{
    int idx = blockIdx.x * 256 + threadIdx.x;
    if (idx >= rows * 128) return;
    int r, c; uint2 H, L;
    split_core(in, idx, r, c, H, L);
    size_t base = (size_t)r * KK;
    *reinterpret_cast<uint2*>(out + base + c)        = H;
    *reinterpret_cast<uint2*>(out + base + 512 + c)  = L;
    *reinterpret_cast<uint2*>(out + base + 1024 + c) = H;
}

// one launch for all four weight matrices (blockIdx.y selects)
__global__ void split3_w4(const float* __restrict__ Wq, const float* __restrict__ Wk,
                          const float* __restrict__ Wv, const float* __restrict__ Wp,
                          __nv_bfloat16* __restrict__ Bq, __nv_bfloat16* __restrict__ Bo)
{
    const int which = blockIdx.y;
    const float* src = (which == 0) ? Wq : (which == 1) ? Wk : (which == 2) ? Wv : Wp;
    __nv_bfloat16* dst = (which == 0) ? Bq
                       : (which == 1) ? Bq + (size_t)512 * KK
                       : (which == 2) ? Bq + (size_t)1024 * KK
                       : Bo;
    int idx = blockIdx.x * 256 + threadIdx.x;
    if (idx >= CC * 128) return;
    int r, c; uint2 H, L;
    split_core(src, idx, r, c, H, L);
    size_t base = (size_t)r * KK;
    *reinterpret_cast<uint2*>(dst + base + c)        = H;
    *reinterpret_cast<uint2*>(dst + base + 512 + c)  = H;
    *reinterpret_cast<uint2*>(dst + base + 1024 + c) = L;
}

// ---------------------------------------------------------------------------
// HMMA GEMM (unchanged): CTA 128x128, BK=32, 4-stage cp.async, ldmatrix.
// ---------------------------------------------------------------------------
#define BK      32
#define PAD     40
#define STAGES  4
#define TILEBF  (128 * PAD)
#define STAGEB  (2 * TILEBF * 2)
#define NKCH    (KK / BK)              // 48

__global__ void __launch_bounds__(256, 2)
gemm_hmma(const __nv_bfloat16* __restrict__ Ag,
          const __nv_bfloat16* __restrict__ Bg,
          float* __restrict__ C, int ldc, const float* __restrict__ bias)
{
    extern __shared__ __align__(16) char smem[];
    const uint32_t sbase = smem_u32(smem);

    const int tid  = threadIdx.x;
    const int wid  = tid >> 5;
    const int lane = tid & 31;
    const int g    = lane >> 2;
    const int tig  = lane & 3;

    const int bm = blockIdx.y * 128;
    const int bn = blockIdx.x * 128;
    const int wm = (wid & 1) * 64;
    const int wn = (wid >> 1) * 32;

    const int r0 = tid >> 1;
    const int c0 = (tid & 1) * 16;

    auto load_stage = [&](int kt, int s) {
        const uint32_t aoff = sbase + (uint32_t)(s * TILEBF + r0 * PAD + c0) * 2;
        const uint32_t boff = aoff + (uint32_t)(STAGES * TILEBF) * 2;
        const __nv_bfloat16* ap = Ag + (size_t)(bm + r0) * KK + kt * BK + c0;
        const __nv_bfloat16* bp = Bg + (size_t)(bn + r0) * KK + kt * BK + c0;
        CP16(aoff,      ap);
        CP16(aoff + 16, ap + 8);
        CP16(boff,      bp);
        CP16(boff + 16, bp + 8);
    };

    const uint32_t a_off = (uint32_t)((wm + (lane & 15)) * PAD + (lane >> 4) * 8) * 2;
    const uint32_t b_off = (uint32_t)((wn + (lane >> 4) * 8 + (lane & 7)) * PAD
                                      + ((lane >> 3) & 1) * 8) * 2;

    float acc[4][4][4] = {};

    load_stage(0, 0); CP_COMMIT();
    load_stage(1, 1); CP_COMMIT();
    load_stage(2, 2); CP_COMMIT();

    for (int kt = 0; kt < NKCH; kt++) {
        CP_WAITG(2);
        __syncthreads();

        const int nk = kt + STAGES - 1;
        if (nk < NKCH) load_stage(nk, nk & 3);
        CP_COMMIT();

        const uint32_t at = sbase + (uint32_t)((kt & 3) * TILEBF) * 2 + a_off;
        const uint32_t bt = sbase + (uint32_t)((STAGES + (kt & 3)) * TILEBF) * 2 + b_off;

        #pragma unroll
        for (int kk = 0; kk < BK; kk += 16) {
            uint32_t af[4][4], bf[4][2];
            #pragma unroll
            for (int mi = 0; mi < 4; mi++)
                LDSM_X4(af[mi][0], af[mi][1], af[mi][2], af[mi][3],
                        at + (uint32_t)(mi * 16 * PAD + kk) * 2);
            #pragma unroll
            for (int np = 0; np < 2; np++)
                LDSM_X4(bf[2*np][0], bf[2*np][1], bf[2*np+1][0], bf[2*np+1][1],
                        bt + (uint32_t)(np * 16 * PAD + kk) * 2);
            #pragma unroll
            for (int mi = 0; mi < 4; mi++)
                #pragma unroll
                for (int ni = 0; ni < 4; ni++)
                    mma16816(acc[mi][ni], af[mi], bf[ni]);
        }
        __syncthreads();
    }

    #pragma unroll
    for (int mi = 0; mi < 4; mi++) {
        const int row0 = bm + wm + mi * 16 + g;
        #pragma unroll
        for (int ni = 0; ni < 4; ni++) {
            const int col = bn + wn + ni * 8 + tig * 2;
            float b0 = 0.f, b1 = 0.f;
            if (bias) { b0 = bias[col]; b1 = bias[col + 1]; }
            float2 lo = make_float2(acc[mi][ni][0] + b0, acc[mi][ni][1] + b1);
            float2 hi = make_float2(acc[mi][ni][2] + b0, acc[mi][ni][3] + b1);
            *reinterpret_cast<float2*>(C + (size_t)row0 * ldc + col)       = lo;
            *reinterpret_cast<float2*>(C + (size_t)(row0 + 8) * ldc + col) = hi;
        }
    }
}

// ---------------------------------------------------------------------------
// Tiled sparse triplane attention, software-pipelined across heads.
// Block = (b, p, 4x4 query tile); 16 queries share a 256-key union.
// Single K buffer + single V buffer; after QK(h) the K buffer is dead ->
// K(h+1) streams in during PV(h); after PV(h), V(h+1) streams during QK(h+1).
// cp.async group discipline: groups alternate [K][V][K][V]...; wait_group(1)
// +__syncthreads before each consume.  Every thread issues exactly 16 CP16
// per phase, keeping per-thread group counts aligned.
// ---------------------------------------------------------------------------
#define QROW 520        // Qs row stride (floats)
#define KROW 68         // Ks/Vs row stride (floats)

__global__ void __launch_bounds__(256, 1)
attn_tile(const float* __restrict__ qkv, __nv_bfloat16* __restrict__ Aout)
{
    extern __shared__ __align__(16) float sm[];
    float* Qs = sm;                         // [16][QROW]
    float* Ks = sm + 16 * QROW;             // [256][KROW]
    float* Vs = Ks + 256 * KROW;            // [256][KROW]
    const uint32_t ks_base = smem_u32(Ks);
    const uint32_t vs_base = smem_u32(Vs);

    const int x  = blockIdx.x;              // 0..383
    const int b  = x / 192;
    const int r0 = x % 192;
    const int p  = r0 >> 6;
    const int t0 = r0 & 63;
    const int i0 = (t0 >> 3) << 2;
    const int j0 = (t0 & 7) << 2;

    const int tid  = threadIdx.x;
    const int wid  = tid >> 5;
    const int lane = tid & 31;

    const float* Bq = qkv + (size_t)b * NN * NQKV;

    // global row index for this thread's 16-row slice of the 256-key union
    const int rr = tid & 255;               // smem row this thread fills (one per c4 loop)
    // precompute global rows once (same for all heads)
    int grow;
    {
        const int rl = rr & 127;
        if (p == 0)
            grow = (rr < 128) ? (1024 + 32 * i0 + rl) : (2048 + 32 * j0 + rl);
        else if (p == 1)
            grow = (rr < 128) ? (32 * i0 + rl)
                              : (2048 + 32 * (rl & 31) + j0 + (rl >> 5));
        else
            grow = (rr < 128) ? (32 * (rl & 31) + i0 + (rl >> 5))
                              : (1024 + 32 * (rl & 31) + j0 + (rl >> 5));
    }

    // each thread loads 16 x 16B for K phase (row rr, all 16 float4 cols)
    auto load_K = [&](int h) {
        const float* src = Bq + (size_t)grow * NQKV + 512 + h * DD;
        const uint32_t dst = ks_base + (uint32_t)(rr * KROW) * 4;
        #pragma unroll
        for (int c4 = 0; c4 < 16; c4++)
            CP16(dst + c4 * 16, src + c4 * 4);
    };
    auto load_V = [&](int h) {
        const float* src = Bq + (size_t)grow * NQKV + 1024 + h * DD;
        const uint32_t dst = vs_base + (uint32_t)(rr * KROW) * 4;
        #pragma unroll
        for (int c4 = 0; c4 < 16; c4++)
            CP16(dst + c4 * 16, src + c4 * 4);
    };

    // ---- load Q tile (all heads) ----
    for (int idx = tid; idx < 16 * 128; idx += 256) {
        const int q  = idx >> 7;
        const int f4 = idx & 127;
        const int di = q >> 2, dj = q & 3;
        const int n  = (p << 10) + (i0 + di) * 32 + (j0 + dj);
        float4 v = *reinterpret_cast<const float4*>(Bq + (size_t)n * NQKV + f4 * 4);
        *reinterpret_cast<float4*>(Qs + q * QROW + f4 * 4) = v;
    }

    load_K(0); CP_COMMIT();
    load_V(0); CP_COMMIT();

    const int q  = wid * 2;                 // this warp's first query
    const int di0 = q >> 2,      dj0 = q & 3;
    const int di1 = (q+1) >> 2,  dj1 = (q+1) & 3;

    for (int h = 0; h < HH; h++) {
        // ---- wait K(h), compute scores + softmax (probs in regs) ----
        CP_WAITG(1);
        __syncthreads();

        float p0[2], p1[2];                 // probs per query (this lane's 2 keys)
        #pragma unroll
        for (int qq = 0; qq < 2; qq++) {
            const int di = qq ? di1 : di0;
            const int dj = qq ? dj1 : dj0;
            const float4* qv4 = reinterpret_cast<const float4*>(Qs + (q + qq) * QROW + h * DD);
            const float4* k0  = reinterpret_cast<const float4*>(Ks + (di * 32 + lane) * KROW);
            const float4* k1  = reinterpret_cast<const float4*>(Ks + (128 + dj * 32 + lane) * KROW);
            float a0 = 0.f, a1 = 0.f;
            #pragma unroll
            for (int d4 = 0; d4 < 16; d4++) {
                const float4 qd = qv4[d4];
                const float4 ka = k0[d4];
                const float4 kb = k1[d4];
                a0 += qd.x * ka.x + qd.y * ka.y + qd.z * ka.z + qd.w * ka.w;
                a1 += qd.x * kb.x + qd.y * kb.y + qd.z * kb.z + qd.w * kb.w;
            }
            a0 *= 0.125f; a1 *= 0.125f;
            float m = fmaxf(a0, a1);
            #pragma unroll
            for (int off = 16; off; off >>= 1)
                m = fmaxf(m, __shfl_xor_sync(0xffffffffu, m, off));
            const float e0 = __expf(a0 - m), e1 = __expf(a1 - m);
            float s = e0 + e1;
            #pragma unroll
            for (int off = 16; off; off >>= 1)
                s += __shfl_xor_sync(0xffffffffu, s, off);
            const float inv = 1.0f / s;
            p0[qq] = e0 * inv;
            p1[qq] = e1 * inv;
        }

        // ---- K buffer dead: start K(h+1) while we do PV(h) ----
        __syncthreads();
        if (h + 1 < HH) { load_K(h + 1); }
        CP_COMMIT();

        // ---- wait V(h), compute PV ----
        CP_WAITG(1);
        __syncthreads();

        float o0[2], o1[2];
        #pragma unroll
        for (int qq = 0; qq < 2; qq++) {
            const int di = qq ? di1 : di0;
            const int dj = qq ? dj1 : dj0;
            float a0 = 0.f, a1 = 0.f;
            const float* v0 = Vs + (di * 32) * KROW;
            const float* v1 = Vs + (128 + dj * 32) * KROW;
            #pragma unroll
            for (int t = 0; t < 32; t++) {
                const float pt = __shfl_sync(0xffffffffu, p0[qq], t);
                a0 += pt * v0[t * KROW + lane];
                a1 += pt * v0[t * KROW + lane + 32];
            }
            #pragma unroll
            for (int t = 0; t < 32; t++) {
                const float pt = __shfl_sync(0xffffffffu, p1[qq], t);
                a0 += pt * v1[t * KROW + lane];
                a1 += pt * v1[t * KROW + lane + 32];
            }
            o0[qq] = a0; o1[qq] = a1;
        }

        // ---- V buffer dead: start V(h+1) while we write output ----
        __syncthreads();
        if (h + 1 < HH) { load_V(h + 1); }
        CP_COMMIT();

        // ---- fused [hi|lo|hi] split write (registers only) ----
        #pragma unroll
        for (int qq = 0; qq < 2; qq++) {
            const int di = qq ? di1 : di0;
            const int dj = qq ? dj1 : dj0;
            const int n = (p << 10) + (i0 + di) * 32 + (j0 + dj);
            const size_t ab = (size_t)(b * NN + n) * KK + h * DD;
            const __nv_bfloat16 h0 = __float2bfloat16(o0[qq]);
            const __nv_bfloat16 l0 = __float2bfloat16(o0[qq] - __bfloat162float(h0));
            const __nv_bfloat16 h1 = __float2bfloat16(o1[qq]);
            const __nv_bfloat16 l1 = __float2bfloat16(o1[qq] - __bfloat162float(h1));
            Aout[ab + lane]             = h0;
            Aout[ab + 512 + lane]       = l0;
            Aout[ab + 1024 + lane]      = h0;
            Aout[ab + lane + 32]        = h1;
            Aout[ab + 512 + lane + 32]  = l1;
            Aout[ab + 1024 + lane + 32] = h1;
        }
    }
}

// ---------------------------------------------------------------------------
// Host side
// ---------------------------------------------------------------------------
extern "C" void kernel_launch(void* const* d_in, const int* in_sizes, int n_in,
                              void* d_out, int out_size)
{
    const float* x  = (const float*)d_in[0];
    const float* Wq = (const float*)d_in[1];
    const float* Wk = (const float*)d_in[2];
    const float* Wv = (const float*)d_in[3];
    const float* Wp = (const float*)d_in[4];
    const float* bp = (const float*)d_in[5];
    float* out = (float*)d_out;

    __nv_bfloat16 *A, *Bq, *Bo;
    float *qkv;
    cudaGetSymbolAddress((void**)&A,   g_A);
    cudaGetSymbolAddress((void**)&Bq,  g_Bqkv);
    cudaGetSymbolAddress((void**)&Bo,  g_Bout);
    cudaGetSymbolAddress((void**)&qkv, g_qkv);

    constexpr int SMEM_G = STAGES * STAGEB;                        // 81920
    constexpr int SMEM_A = (16 * QROW + 2 * 256 * KROW) * 4;       // 172544
    static bool s_attr = false;
    if (!s_attr) {
        cudaFuncSetAttribute(gemm_hmma,  cudaFuncAttributeMaxDynamicSharedMemorySize, SMEM_G);
        cudaFuncSetAttribute(attn_tile,  cudaFuncAttributeMaxDynamicSharedMemorySize, SMEM_A);
        s_attr = true;
    }

    // 1) hi/lo splits (activations + all four weights in one launch)
    split3_a<<<(MM * 128 + 255) / 256, 256>>>(x, A, MM);
    split3_w4<<<dim3((CC * 128 + 255) / 256, 4), 256>>>(Wq, Wk, Wv, Wp, Bq, Bo);

    // 2) fused QKV projection
    gemm_hmma<<<dim3(NQKV / 128, MM / 128), 256, SMEM_G>>>(A, Bq, qkv, NQKV, nullptr);

    // 3) tiled sparse attention, head-pipelined (writes split A directly)
    attn_tile<<<NB * 3 * 64, 256, SMEM_A>>>(qkv, A);

    // 4) output projection with bias
    gemm_hmma<<<dim3(CC / 128, MM / 128), 256, SMEM_G>>>(A, Bo, out, CC, bp);
}

// round 9
// speedup vs baseline: 1.2926x; 1.2926x over previous
#include <cuda_runtime.h>
#include <cuda_bf16.h>
#include <cstdint>
#include <cstddef>

#define NB   2
#define NN   3072
#define CC   512
#define MM   (NB * NN)      // 6144
#define HH   8
#define DD   64
#define KK   1536           // split-K: A=[hi|lo|hi], B=[hi|hi|lo]
#define NQKV 1536

// ---------------------------------------------------------------------------
// Device scratch
// ---------------------------------------------------------------------------
__device__ __align__(1024) __nv_bfloat16 g_A[(size_t)MM * KK];      // split activations
__device__ __align__(1024) __nv_bfloat16 g_Bqkv[(size_t)NQKV * KK]; // [Wq;Wk;Wv] split
__device__ __align__(1024) __nv_bfloat16 g_Bout[(size_t)CC * KK];   // Wp split
__device__ __align__(16)   float g_qkv[(size_t)MM * NQKV];          // q|k|v fp32

// ---------------------------------------------------------------------------
// helpers
// ---------------------------------------------------------------------------
__device__ __forceinline__ uint32_t smem_u32(const void* p) {
    uint32_t a;
    asm("{ .reg .u64 t; cvta.to.shared.u64 t, %1; cvt.u32.u64 %0, t; }" : "=r"(a) : "l"(p));
    return a;
}

#define CP16(dst_u32, src_ptr) \
    asm volatile("cp.async.cg.shared.global [%0], [%1], 16;" :: "r"(dst_u32), "l"(src_ptr))
#define CP_COMMIT()  asm volatile("cp.async.commit_group;" ::: "memory")
#define CP_WAITG(n)  asm volatile("cp.async.wait_group %0;" :: "n"(n) : "memory")

#define LDSM_X4(r0, r1, r2, r3, addr) \
    asm volatile("ldmatrix.sync.aligned.m8n8.x4.shared.b16 {%0,%1,%2,%3}, [%4];" \
                 : "=r"(r0), "=r"(r1), "=r"(r2), "=r"(r3) : "r"(addr))

__device__ __forceinline__ void mma16816(float* c, const uint32_t* a, const uint32_t* b) {
    asm volatile(
        "mma.sync.aligned.m16n8k16.row.col.f32.bf16.bf16.f32 "
        "{%0,%1,%2,%3}, {%4,%5,%6,%7}, {%8,%9}, {%0,%1,%2,%3};"
        : "+f"(c[0]), "+f"(c[1]), "+f"(c[2]), "+f"(c[3])
        : "r"(a[0]), "r"(a[1]), "r"(a[2]), "r"(a[3]), "r"(b[0]), "r"(b[1]));
}

// ---------------------------------------------------------------------------
// Hi/lo splitters:  activations -> [hi|lo|hi], weights -> [hi|hi|lo]
// ---------------------------------------------------------------------------
__device__ __forceinline__ void split_core(const float* __restrict__ in, int idx,
                                           int& r, int& c, uint2& H, uint2& L)
{
    r = idx >> 7;
    c = (idx & 127) << 2;
    float4 v = *reinterpret_cast<const float4*>(in + (size_t)r * CC + c);
    float f[4] = {v.x, v.y, v.z, v.w};
    uint32_t h[2], l[2];
    #pragma unroll
    for (int i = 0; i < 2; i++) {
        __nv_bfloat16 h0 = __float2bfloat16(f[2*i]);
        __nv_bfloat16 h1 = __float2bfloat16(f[2*i + 1]);
        __nv_bfloat16 l0 = __float2bfloat16(f[2*i]     - __bfloat162float(h0));
        __nv_bfloat16 l1 = __float2bfloat16(f[2*i + 1] - __bfloat162float(h1));
        h[i] = (uint32_t)__bfloat16_as_ushort(h0) | ((uint32_t)__bfloat16_as_ushort(h1) << 16);
        l[i] = (uint32_t)__bfloat16_as_ushort(l0) | ((uint32_t)__bfloat16_as_ushort(l1) << 16);
    }
    H = make_uint2(h[0], h[1]);
    L = make_uint2(l[0], l[1]);
}

__global__ void split3_a(const float* __restrict__ in, __nv_bfloat16* __restrict__ out, int rows)
{
    int idx = blockIdx.x * 256 + threadIdx.x;
    if (idx >= rows * 128) return;
    int r, c; uint2 H, L;
    split_core(in, idx, r, c, H, L);
    size_t base = (size_t)r * KK;
    *reinterpret_cast<uint2*>(out + base + c)        = H;
    *reinterpret_cast<uint2*>(out + base + 512 + c)  = L;
    *reinterpret_cast<uint2*>(out + base + 1024 + c) = H;
}

__global__ void split3_w4(const float* __restrict__ Wq, const float* __restrict__ Wk,
                          const float* __restrict__ Wv, const float* __restrict__ Wp,
                          __nv_bfloat16* __restrict__ Bq, __nv_bfloat16* __restrict__ Bo)
{
    const int which = blockIdx.y;
    const float* src = (which == 0) ? Wq : (which == 1) ? Wk : (which == 2) ? Wv : Wp;
    __nv_bfloat16* dst = (which == 0) ? Bq
                       : (which == 1) ? Bq + (size_t)512 * KK
                       : (which == 2) ? Bq + (size_t)1024 * KK
                       : Bo;
    int idx = blockIdx.x * 256 + threadIdx.x;
    if (idx >= CC * 128) return;
    int r, c; uint2 H, L;
    split_core(src, idx, r, c, H, L);
    size_t base = (size_t)r * KK;
    *reinterpret_cast<uint2*>(dst + base + c)        = H;
    *reinterpret_cast<uint2*>(dst + base + 512 + c)  = H;
    *reinterpret_cast<uint2*>(dst + base + 1024 + c) = L;
}

// ---------------------------------------------------------------------------
// HMMA GEMM (unchanged): CTA 128x128, BK=32, 4-stage cp.async, ldmatrix.
// ---------------------------------------------------------------------------
#define BK      32
#define PAD     40
#define STAGES  4
#define TILEBF  (128 * PAD)
#define STAGEB  (2 * TILEBF * 2)
#define NKCH    (KK / BK)              // 48

__global__ void __launch_bounds__(256, 2)
gemm_hmma(const __nv_bfloat16* __restrict__ Ag,
          const __nv_bfloat16* __restrict__ Bg,
          float* __restrict__ C, int ldc, const float* __restrict__ bias)
{
    extern __shared__ __align__(16) char smem[];
    const uint32_t sbase = smem_u32(smem);

    const int tid  = threadIdx.x;
    const int wid  = tid >> 5;
    const int lane = tid & 31;
    const int g    = lane >> 2;
    const int tig  = lane & 3;

    const int bm = blockIdx.y * 128;
    const int bn = blockIdx.x * 128;
    const int wm = (wid & 1) * 64;
    const int wn = (wid >> 1) * 32;

    const int r0 = tid >> 1;
    const int c0 = (tid & 1) * 16;

    auto load_stage = [&](int kt, int s) {
        const uint32_t aoff = sbase + (uint32_t)(s * TILEBF + r0 * PAD + c0) * 2;
        const uint32_t boff = aoff + (uint32_t)(STAGES * TILEBF) * 2;
        const __nv_bfloat16* ap = Ag + (size_t)(bm + r0) * KK + kt * BK + c0;
        const __nv_bfloat16* bp = Bg + (size_t)(bn + r0) * KK + kt * BK + c0;
        CP16(aoff,      ap);
        CP16(aoff + 16, ap + 8);
        CP16(boff,      bp);
        CP16(boff + 16, bp + 8);
    };

    const uint32_t a_off = (uint32_t)((wm + (lane & 15)) * PAD + (lane >> 4) * 8) * 2;
    const uint32_t b_off = (uint32_t)((wn + (lane >> 4) * 8 + (lane & 7)) * PAD
                                      + ((lane >> 3) & 1) * 8) * 2;

    float acc[4][4][4] = {};

    load_stage(0, 0); CP_COMMIT();
    load_stage(1, 1); CP_COMMIT();
    load_stage(2, 2); CP_COMMIT();

    for (int kt = 0; kt < NKCH; kt++) {
        CP_WAITG(2);
        __syncthreads();

        const int nk = kt + STAGES - 1;
        if (nk < NKCH) load_stage(nk, nk & 3);
        CP_COMMIT();

        const uint32_t at = sbase + (uint32_t)((kt & 3) * TILEBF) * 2 + a_off;
        const uint32_t bt = sbase + (uint32_t)((STAGES + (kt & 3)) * TILEBF) * 2 + b_off;

        #pragma unroll
        for (int kk = 0; kk < BK; kk += 16) {
            uint32_t af[4][4], bf[4][2];
            #pragma unroll
            for (int mi = 0; mi < 4; mi++)
                LDSM_X4(af[mi][0], af[mi][1], af[mi][2], af[mi][3],
                        at + (uint32_t)(mi * 16 * PAD + kk) * 2);
            #pragma unroll
            for (int np = 0; np < 2; np++)
                LDSM_X4(bf[2*np][0], bf[2*np][1], bf[2*np+1][0], bf[2*np+1][1],
                        bt + (uint32_t)(np * 16 * PAD + kk) * 2);
            #pragma unroll
            for (int mi = 0; mi < 4; mi++)
                #pragma unroll
                for (int ni = 0; ni < 4; ni++)
                    mma16816(acc[mi][ni], af[mi], bf[ni]);
        }
        __syncthreads();
    }

    #pragma unroll
    for (int mi = 0; mi < 4; mi++) {
        const int row0 = bm + wm + mi * 16 + g;
        #pragma unroll
        for (int ni = 0; ni < 4; ni++) {
            const int col = bn + wn + ni * 8 + tig * 2;
            float b0 = 0.f, b1 = 0.f;
            if (bias) { b0 = bias[col]; b1 = bias[col + 1]; }
            float2 lo = make_float2(acc[mi][ni][0] + b0, acc[mi][ni][1] + b1);
            float2 hi = make_float2(acc[mi][ni][2] + b0, acc[mi][ni][3] + b1);
            *reinterpret_cast<float2*>(C + (size_t)row0 * ldc + col)       = lo;
            *reinterpret_cast<float2*>(C + (size_t)(row0 + 8) * ldc + col) = hi;
        }
    }
}

// ---------------------------------------------------------------------------
// Tiled sparse triplane attention, occupancy-first version.
// Block = (b, p, 4x4 query tile); 16 queries share a 256-key union.
// ONE 256-row buffer reused K->V within each head + per-head Q stage.
// smem ~73KB -> 3 CTAs/SM; latency hidden by co-resident CTAs, not
// intra-CTA pipelining (R8's lesson).
// ---------------------------------------------------------------------------
#define KROW 68         // buffer row stride (floats): 16B-aligned, low-conflict

__global__ void __launch_bounds__(256, 3)
attn_tile(const float* __restrict__ qkv, __nv_bfloat16* __restrict__ Aout)
{
    extern __shared__ __align__(16) float sm[];
    float* Ks    = sm;                         // [256][KROW] (K, then V)
    float* Qh    = sm + 256 * KROW;            // [16][KROW]
    int*   growS = (int*)(Qh + 16 * KROW);     // [256] global row per buffer row
    const uint32_t ks_base = smem_u32(Ks);
    const uint32_t qh_base = smem_u32(Qh);

    const int x  = blockIdx.x;                 // 0..383
    const int b  = x / 192;
    const int r0 = x % 192;
    const int p  = r0 >> 6;
    const int t0 = r0 & 63;
    const int i0 = (t0 >> 3) << 2;
    const int j0 = (t0 & 7) << 2;

    const int tid  = threadIdx.x;
    const int wid  = tid >> 5;
    const int lane = tid & 31;

    const float* Bq = qkv + (size_t)b * NN * NQKV;

    // precompute the key-union row table once
    {
        const int rr = tid;
        const int rl = rr & 127;
        int gr;
        if (p == 0)
            gr = (rr < 128) ? (1024 + 32 * i0 + rl) : (2048 + 32 * j0 + rl);
        else if (p == 1)
            gr = (rr < 128) ? (32 * i0 + rl)
                            : (2048 + 32 * (rl & 31) + j0 + (rl >> 5));
        else
            gr = (rr < 128) ? (32 * (rl & 31) + i0 + (rl >> 5))
                            : (1024 + 32 * (rl & 31) + j0 + (rl >> 5));
        growS[rr] = gr;
    }
    __syncthreads();

    const int q   = wid * 2;
    const int di0 = q >> 2,       dj0 = q & 3;
    const int di1 = (q + 1) >> 2, dj1 = (q + 1) & 3;
    const int c4t = tid & 15;

    for (int h = 0; h < HH; h++) {
        // ---- phase A: stage K (+ Q) for head h ----
        #pragma unroll
        for (int it = 0; it < 16; it++) {
            const int rr = it * 16 + (tid >> 4);
            const float* src = Bq + (size_t)growS[rr] * NQKV + 512 + h * DD + c4t * 4;
            CP16(ks_base + (uint32_t)(rr * KROW + c4t * 4) * 4, src);
        }
        {
            const int qr = tid >> 4;
            const int n  = (p << 10) + (i0 + (qr >> 2)) * 32 + (j0 + (qr & 3));
            CP16(qh_base + (uint32_t)(qr * KROW + c4t * 4) * 4,
                 Bq + (size_t)n * NQKV + h * DD + c4t * 4);
        }
        CP_COMMIT(); CP_WAITG(0);
        __syncthreads();

        // ---- QK + softmax (probs stay in regs) ----
        float p0[2], p1[2];
        #pragma unroll
        for (int qq = 0; qq < 2; qq++) {
            const int di = qq ? di1 : di0;
            const int dj = qq ? dj1 : dj0;
            const float4* qv4 = reinterpret_cast<const float4*>(Qh + (q + qq) * KROW);
            const float4* k0  = reinterpret_cast<const float4*>(Ks + (di * 32 + lane) * KROW);
            const float4* k1  = reinterpret_cast<const float4*>(Ks + (128 + dj * 32 + lane) * KROW);
            float a0 = 0.f, a1 = 0.f;
            #pragma unroll
            for (int d4 = 0; d4 < 16; d4++) {
                const float4 qd = qv4[d4];
                const float4 ka = k0[d4];
                const float4 kb = k1[d4];
                a0 += qd.x * ka.x + qd.y * ka.y + qd.z * ka.z + qd.w * ka.w;
                a1 += qd.x * kb.x + qd.y * kb.y + qd.z * kb.z + qd.w * kb.w;
            }
            a0 *= 0.125f; a1 *= 0.125f;
            float m = fmaxf(a0, a1);
            #pragma unroll
            for (int off = 16; off; off >>= 1)
                m = fmaxf(m, __shfl_xor_sync(0xffffffffu, m, off));
            const float e0 = __expf(a0 - m), e1 = __expf(a1 - m);
            float s = e0 + e1;
            #pragma unroll
            for (int off = 16; off; off >>= 1)
                s += __shfl_xor_sync(0xffffffffu, s, off);
            const float inv = 1.0f / s;
            p0[qq] = e0 * inv;
            p1[qq] = e1 * inv;
        }
        __syncthreads();   // K reads done; buffer free for V

        // ---- phase B: stage V into the same buffer ----
        #pragma unroll
        for (int it = 0; it < 16; it++) {
            const int rr = it * 16 + (tid >> 4);
            const float* src = Bq + (size_t)growS[rr] * NQKV + 1024 + h * DD + c4t * 4;
            CP16(ks_base + (uint32_t)(rr * KROW + c4t * 4) * 4, src);
        }
        CP_COMMIT(); CP_WAITG(0);
        __syncthreads();

        // ---- PV ----
        float o0[2], o1[2];
        #pragma unroll
        for (int qq = 0; qq < 2; qq++) {
            const int di = qq ? di1 : di0;
            const int dj = qq ? dj1 : dj0;
            float a0 = 0.f, a1 = 0.f;
            const float* v0 = Ks + (di * 32) * KROW;
            const float* v1 = Ks + (128 + dj * 32) * KROW;
            #pragma unroll
            for (int t = 0; t < 32; t++) {
                const float pt = __shfl_sync(0xffffffffu, p0[qq], t);
                a0 += pt * v0[t * KROW + lane];
                a1 += pt * v0[t * KROW + lane + 32];
            }
            #pragma unroll
            for (int t = 0; t < 32; t++) {
                const float pt = __shfl_sync(0xffffffffu, p1[qq], t);
                a0 += pt * v1[t * KROW + lane];
                a1 += pt * v1[t * KROW + lane + 32];
            }
            o0[qq] = a0; o1[qq] = a1;
        }
        __syncthreads();   // V reads done before next head's K overwrites

        // ---- fused [hi|lo|hi] split write ----
        #pragma unroll
        for (int qq = 0; qq < 2; qq++) {
            const int di = qq ? di1 : di0;
            const int dj = qq ? dj1 : dj0;
            const int n = (p << 10) + (i0 + di) * 32 + (j0 + dj);
            const size_t ab = (size_t)(b * NN + n) * KK + h * DD;
            const __nv_bfloat16 h0 = __float2bfloat16(o0[qq]);
            const __nv_bfloat16 l0 = __float2bfloat16(o0[qq] - __bfloat162float(h0));
            const __nv_bfloat16 h1 = __float2bfloat16(o1[qq]);
            const __nv_bfloat16 l1 = __float2bfloat16(o1[qq] - __bfloat162float(h1));
            Aout[ab + lane]             = h0;
            Aout[ab + 512 + lane]       = l0;
            Aout[ab + 1024 + lane]      = h0;
            Aout[ab + lane + 32]        = h1;
            Aout[ab + 512 + lane + 32]  = l1;
            Aout[ab + 1024 + lane + 32] = h1;
        }
    }
}

// ---------------------------------------------------------------------------
// Host side
// ---------------------------------------------------------------------------
extern "C" void kernel_launch(void* const* d_in, const int* in_sizes, int n_in,
                              void* d_out, int out_size)
{
    const float* x  = (const float*)d_in[0];
    const float* Wq = (const float*)d_in[1];
    const float* Wk = (const float*)d_in[2];
    const float* Wv = (const float*)d_in[3];
    const float* Wp = (const float*)d_in[4];
    const float* bp = (const float*)d_in[5];
    float* out = (float*)d_out;

    __nv_bfloat16 *A, *Bq, *Bo;
    float *qkv;
    cudaGetSymbolAddress((void**)&A,   g_A);
    cudaGetSymbolAddress((void**)&Bq,  g_Bqkv);
    cudaGetSymbolAddress((void**)&Bo,  g_Bout);
    cudaGetSymbolAddress((void**)&qkv, g_qkv);

    constexpr int SMEM_G = STAGES * STAGEB;                         // 81920
    constexpr int SMEM_A = (256 * KROW + 16 * KROW) * 4 + 256 * 4;  // 75008
    static bool s_attr = false;
    if (!s_attr) {
        cudaFuncSetAttribute(gemm_hmma,  cudaFuncAttributeMaxDynamicSharedMemorySize, SMEM_G);
        cudaFuncSetAttribute(attn_tile,  cudaFuncAttributeMaxDynamicSharedMemorySize, SMEM_A);
        s_attr = true;
    }

    // 1) hi/lo splits
    split3_a<<<(MM * 128 + 255) / 256, 256>>>(x, A, MM);
    split3_w4<<<dim3((CC * 128 + 255) / 256, 4), 256>>>(Wq, Wk, Wv, Wp, Bq, Bo);

    // 2) fused QKV projection
    gemm_hmma<<<dim3(NQKV / 128, MM / 128), 256, SMEM_G>>>(A, Bq, qkv, NQKV, nullptr);

    // 3) tiled sparse attention, occupancy-first (writes split A directly)
    attn_tile<<<NB * 3 * 64, 256, SMEM_A>>>(qkv, A);

    // 4) output projection with bias
    gemm_hmma<<<dim3(CC / 128, MM / 128), 256, SMEM_G>>>(A, Bo, out, CC, bp);
}

// round 10
// speedup vs baseline: 1.4480x; 1.1202x over previous
#include <cuda_runtime.h>
#include <cuda_bf16.h>
#include <cstdint>
#include <cstddef>

#define NB   2
#define NN   3072
#define CC   512
#define MM   (NB * NN)      // 6144
#define HH   8
#define DD   64
#define KK   1536           // split-K: A=[hi|lo|hi], B=[hi|hi|lo]
#define NQKV 1536

// ---------------------------------------------------------------------------
// Device scratch
// ---------------------------------------------------------------------------
__device__ __align__(1024) __nv_bfloat16 g_A[(size_t)MM * KK];      // split activations
__device__ __align__(1024) __nv_bfloat16 g_Bqkv[(size_t)NQKV * KK]; // [Wq;Wk;Wv] split
__device__ __align__(1024) __nv_bfloat16 g_Bout[(size_t)CC * KK];   // Wp split
__device__ __align__(16)   float g_qkv[(size_t)MM * NQKV];          // q|k|v fp32

// ---------------------------------------------------------------------------
// helpers
// ---------------------------------------------------------------------------
__device__ __forceinline__ uint32_t smem_u32(const void* p) {
    uint32_t a;
    asm("{ .reg .u64 t; cvta.to.shared.u64 t, %1; cvt.u32.u64 %0, t; }" : "=r"(a) : "l"(p));
    return a;
}

#define CP16(dst_u32, src_ptr) \
    asm volatile("cp.async.cg.shared.global [%0], [%1], 16;" :: "r"(dst_u32), "l"(src_ptr))
#define CP_COMMIT()  asm volatile("cp.async.commit_group;" ::: "memory")
#define CP_WAITG(n)  asm volatile("cp.async.wait_group %0;" :: "n"(n) : "memory")

#define LDSM_X4(r0, r1, r2, r3, addr) \
    asm volatile("ldmatrix.sync.aligned.m8n8.x4.shared.b16 {%0,%1,%2,%3}, [%4];" \
                 : "=r"(r0), "=r"(r1), "=r"(r2), "=r"(r3) : "r"(addr))

__device__ __forceinline__ void mma16816(float* c, const uint32_t* a, const uint32_t* b) {
    asm volatile(
        "mma.sync.aligned.m16n8k16.row.col.f32.bf16.bf16.f32 "
        "{%0,%1,%2,%3}, {%4,%5,%6,%7}, {%8,%9}, {%0,%1,%2,%3};"
        : "+f"(c[0]), "+f"(c[1]), "+f"(c[2]), "+f"(c[3])
        : "r"(a[0]), "r"(a[1]), "r"(a[2]), "r"(a[3]), "r"(b[0]), "r"(b[1]));
}

// ---------------------------------------------------------------------------
// Hi/lo splitters:  activations -> [hi|lo|hi], weights -> [hi|hi|lo]
// ---------------------------------------------------------------------------
__device__ __forceinline__ void split_core(const float* __restrict__ in, int idx,
                                           int& r, int& c, uint2& H, uint2& L)
{
    r = idx >> 7;
    c = (idx & 127) << 2;
    float4 v = *reinterpret_cast<const float4*>(in + (size_t)r * CC + c);
    float f[4] = {v.x, v.y, v.z, v.w};
    uint32_t h[2], l[2];
    #pragma unroll
    for (int i = 0; i < 2; i++) {
        __nv_bfloat16 h0 = __float2bfloat16(f[2*i]);
        __nv_bfloat16 h1 = __float2bfloat16(f[2*i + 1]);
        __nv_bfloat16 l0 = __float2bfloat16(f[2*i]     - __bfloat162float(h0));
        __nv_bfloat16 l1 = __float2bfloat16(f[2*i + 1] - __bfloat162float(h1));
        h[i] = (uint32_t)__bfloat16_as_ushort(h0) | ((uint32_t)__bfloat16_as_ushort(h1) << 16);
        l[i] = (uint32_t)__bfloat16_as_ushort(l0) | ((uint32_t)__bfloat16_as_ushort(l1) << 16);
    }
    H = make_uint2(h[0], h[1]);
    L = make_uint2(l[0], l[1]);
}

__global__ void split3_a(const float* __restrict__ in, __nv_bfloat16* __restrict__ out, int rows)
{
    int idx = blockIdx.x * 256 + threadIdx.x;
    if (idx >= rows * 128) return;
    int r, c; uint2 H, L;
    split_core(in, idx, r, c, H, L);
    size_t base = (size_t)r * KK;
    *reinterpret_cast<uint2*>(out + base + c)        = H;
    *reinterpret_cast<uint2*>(out + base + 512 + c)  = L;
    *reinterpret_cast<uint2*>(out + base + 1024 + c) = H;
}

__global__ void split3_w4(const float* __restrict__ Wq, const float* __restrict__ Wk,
                          const float* __restrict__ Wv, const float* __restrict__ Wp,
                          __nv_bfloat16* __restrict__ Bq, __nv_bfloat16* __restrict__ Bo)
{
    const int which = blockIdx.y;
    const float* src = (which == 0) ? Wq : (which == 1) ? Wk : (which == 2) ? Wv : Wp;
    __nv_bfloat16* dst = (which == 0) ? Bq
                       : (which == 1) ? Bq + (size_t)512 * KK
                       : (which == 2) ? Bq + (size_t)1024 * KK
                       : Bo;
    int idx = blockIdx.x * 256 + threadIdx.x;
    if (idx >= CC * 128) return;
    int r, c; uint2 H, L;
    split_core(src, idx, r, c, H, L);
    size_t base = (size_t)r * KK;
    *reinterpret_cast<uint2*>(dst + base + c)        = H;
    *reinterpret_cast<uint2*>(dst + base + 512 + c)  = H;
    *reinterpret_cast<uint2*>(dst + base + 1024 + c) = L;
}

// ---------------------------------------------------------------------------
// HMMA GEMM (unchanged): CTA 128x128, BK=32, 4-stage cp.async, ldmatrix.
// ---------------------------------------------------------------------------
#define BK      32
#define PAD     40
#define STAGES  4
#define TILEBF  (128 * PAD)
#define STAGEB  (2 * TILEBF * 2)
#define NKCH    (KK / BK)              // 48

__global__ void __launch_bounds__(256, 2)
gemm_hmma(const __nv_bfloat16* __restrict__ Ag,
          const __nv_bfloat16* __restrict__ Bg,
          float* __restrict__ C, int ldc, const float* __restrict__ bias)
{
    extern __shared__ __align__(16) char smem[];
    const uint32_t sbase = smem_u32(smem);

    const int tid  = threadIdx.x;
    const int wid  = tid >> 5;
    const int lane = tid & 31;
    const int g    = lane >> 2;
    const int tig  = lane & 3;

    const int bm = blockIdx.y * 128;
    const int bn = blockIdx.x * 128;
    const int wm = (wid & 1) * 64;
    const int wn = (wid >> 1) * 32;

    const int r0 = tid >> 1;
    const int c0 = (tid & 1) * 16;

    auto load_stage = [&](int kt, int s) {
        const uint32_t aoff = sbase + (uint32_t)(s * TILEBF + r0 * PAD + c0) * 2;
        const uint32_t boff = aoff + (uint32_t)(STAGES * TILEBF) * 2;
        const __nv_bfloat16* ap = Ag + (size_t)(bm + r0) * KK + kt * BK + c0;
        const __nv_bfloat16* bp = Bg + (size_t)(bn + r0) * KK + kt * BK + c0;
        CP16(aoff,      ap);
        CP16(aoff + 16, ap + 8);
        CP16(boff,      bp);
        CP16(boff + 16, bp + 8);
    };

    const uint32_t a_off = (uint32_t)((wm + (lane & 15)) * PAD + (lane >> 4) * 8) * 2;
    const uint32_t b_off = (uint32_t)((wn + (lane >> 4) * 8 + (lane & 7)) * PAD
                                      + ((lane >> 3) & 1) * 8) * 2;

    float acc[4][4][4] = {};

    load_stage(0, 0); CP_COMMIT();
    load_stage(1, 1); CP_COMMIT();
    load_stage(2, 2); CP_COMMIT();

    for (int kt = 0; kt < NKCH; kt++) {
        CP_WAITG(2);
        __syncthreads();

        const int nk = kt + STAGES - 1;
        if (nk < NKCH) load_stage(nk, nk & 3);
        CP_COMMIT();

        const uint32_t at = sbase + (uint32_t)((kt & 3) * TILEBF) * 2 + a_off;
        const uint32_t bt = sbase + (uint32_t)((STAGES + (kt & 3)) * TILEBF) * 2 + b_off;

        #pragma unroll
        for (int kk = 0; kk < BK; kk += 16) {
            uint32_t af[4][4], bf[4][2];
            #pragma unroll
            for (int mi = 0; mi < 4; mi++)
                LDSM_X4(af[mi][0], af[mi][1], af[mi][2], af[mi][3],
                        at + (uint32_t)(mi * 16 * PAD + kk) * 2);
            #pragma unroll
            for (int np = 0; np < 2; np++)
                LDSM_X4(bf[2*np][0], bf[2*np][1], bf[2*np+1][0], bf[2*np+1][1],
                        bt + (uint32_t)(np * 16 * PAD + kk) * 2);
            #pragma unroll
            for (int mi = 0; mi < 4; mi++)
                #pragma unroll
                for (int ni = 0; ni < 4; ni++)
                    mma16816(acc[mi][ni], af[mi], bf[ni]);
        }
        __syncthreads();
    }

    #pragma unroll
    for (int mi = 0; mi < 4; mi++) {
        const int row0 = bm + wm + mi * 16 + g;
        #pragma unroll
        for (int ni = 0; ni < 4; ni++) {
            const int col = bn + wn + ni * 8 + tig * 2;
            float b0 = 0.f, b1 = 0.f;
            if (bias) { b0 = bias[col]; b1 = bias[col + 1]; }
            float2 lo = make_float2(acc[mi][ni][0] + b0, acc[mi][ni][1] + b1);
            float2 hi = make_float2(acc[mi][ni][2] + b0, acc[mi][ni][3] + b1);
            *reinterpret_cast<float2*>(C + (size_t)row0 * ldc + col)       = lo;
            *reinterpret_cast<float2*>(C + (size_t)(row0 + 8) * ldc + col) = hi;
        }
    }
}

// ---------------------------------------------------------------------------
// Tiled sparse triplane attention, key-major warp specialization.
// Block = (b, p, 4x4 query tile); 256-key union in one K/V-reused buffer.
// Warps 0-3 own key-group0 by di (lane = key), computing scores/PV for the
// 4 queries sharing di with ONE read of each K/V row.  Warps 4-7 mirror for
// group1 by dj.  Scores/probs/partial-outputs exchange through a single 4KB
// region that time-multiplexes Qh -> scores -> probs -> oex.
// smem ~73KB -> 3 CTAs/SM.
// ---------------------------------------------------------------------------
#define KROW 68         // K/V buffer row stride (floats)
#define SROW 64         // shared-region row stride (floats)

__global__ void __launch_bounds__(256, 3)
attn_tile(const float* __restrict__ qkv, __nv_bfloat16* __restrict__ Aout)
{
    extern __shared__ __align__(16) float sm[];
    float* Ks    = sm;                         // [256][KROW]  (K, then V)
    float* Sh    = sm + 256 * KROW;            // [16][SROW]   Qh/scores/probs/oex
    int*   growS = (int*)(Sh + 16 * SROW);     // [256]
    const uint32_t ks_base = smem_u32(Ks);
    const uint32_t sh_base = smem_u32(Sh);

    const int x  = blockIdx.x;                 // 0..383
    const int b  = x / 192;
    const int r0 = x % 192;
    const int p  = r0 >> 6;
    const int t0 = r0 & 63;
    const int i0 = (t0 >> 3) << 2;
    const int j0 = (t0 & 7) << 2;

    const int tid  = threadIdx.x;
    const int wid  = tid >> 5;
    const int lane = tid & 31;

    const float* Bq = qkv + (size_t)b * NN * NQKV;

    // key-union row table (once)
    {
        const int rr = tid;
        const int rl = rr & 127;
        int gr;
        if (p == 0)
            gr = (rr < 128) ? (1024 + 32 * i0 + rl) : (2048 + 32 * j0 + rl);
        else if (p == 1)
            gr = (rr < 128) ? (32 * i0 + rl)
                            : (2048 + 32 * (rl & 31) + j0 + (rl >> 5));
        else
            gr = (rr < 128) ? (32 * (rl & 31) + i0 + (rl >> 5))
                            : (1024 + 32 * (rl & 31) + j0 + (rl >> 5));
        growS[rr] = gr;
    }
    __syncthreads();

    const bool g0  = (wid < 4);
    const int  grp = g0 ? wid : (wid - 4);     // di (g0) or dj (g1)
    const int  krow0 = g0 ? (grp * 32) : (128 + grp * 32);
    const int  c4t = tid & 15;

    for (int h = 0; h < HH; h++) {
        // ---- load K (rows 0..255) + Q (16 rows) for head h ----
        #pragma unroll
        for (int it = 0; it < 16; it++) {
            const int rr = it * 16 + (tid >> 4);
            const float* src = Bq + (size_t)growS[rr] * NQKV + 512 + h * DD + c4t * 4;
            CP16(ks_base + (uint32_t)(rr * KROW + c4t * 4) * 4, src);
        }
        {
            const int qr = tid >> 4;
            const int n  = (p << 10) + (i0 + (qr >> 2)) * 32 + (j0 + (qr & 3));
            CP16(sh_base + (uint32_t)(qr * SROW + c4t * 4) * 4,
                 Bq + (size_t)n * NQKV + h * DD + c4t * 4);
        }
        CP_COMMIT(); CP_WAITG(0);
        __syncthreads();                               // S1: K + Qh ready

        // ---- QK: lane = key, 4 queries per warp, K row read ONCE ----
        float s[4] = {0.f, 0.f, 0.f, 0.f};
        {
            const float4* Krow = reinterpret_cast<const float4*>(Ks + (krow0 + lane) * KROW);
            #pragma unroll
            for (int d4 = 0; d4 < 16; d4++) {
                const float4 kv = Krow[d4];
                #pragma unroll
                for (int qq = 0; qq < 4; qq++) {
                    const int q = g0 ? (grp * 4 + qq) : (qq * 4 + grp);
                    const float4 qv = *reinterpret_cast<const float4*>(Sh + q * SROW + d4 * 4);
                    s[qq] += qv.x * kv.x + qv.y * kv.y + qv.z * kv.z + qv.w * kv.w;
                }
            }
        }
        __syncthreads();                               // S2: K + Qh reads done

        // ---- V load starts now (K buffer dead); write scores over Qh ----
        #pragma unroll
        for (int it = 0; it < 16; it++) {
            const int rr = it * 16 + (tid >> 4);
            const float* src = Bq + (size_t)growS[rr] * NQKV + 1024 + h * DD + c4t * 4;
            CP16(ks_base + (uint32_t)(rr * KROW + c4t * 4) * 4, src);
        }
        CP_COMMIT();

        {
            const int slot = g0 ? lane : (32 + lane);
            #pragma unroll
            for (int qq = 0; qq < 4; qq++) {
                const int q = g0 ? (grp * 4 + qq) : (qq * 4 + grp);
                Sh[q * SROW + slot] = s[qq] * 0.125f;
            }
        }
        __syncthreads();                               // S3: scores visible

        // ---- softmax: warp w -> queries 2w, 2w+1; probs written in place ----
        #pragma unroll
        for (int qq = 0; qq < 2; qq++) {
            const int q = wid * 2 + qq;
            float s0 = Sh[q * SROW + lane];
            float s1 = Sh[q * SROW + lane + 32];
            float m = fmaxf(s0, s1);
            #pragma unroll
            for (int off = 16; off; off >>= 1)
                m = fmaxf(m, __shfl_xor_sync(0xffffffffu, m, off));
            const float e0 = __expf(s0 - m), e1 = __expf(s1 - m);
            float su = e0 + e1;
            #pragma unroll
            for (int off = 16; off; off >>= 1)
                su += __shfl_xor_sync(0xffffffffu, su, off);
            const float inv = 1.0f / su;
            Sh[q * SROW + lane]      = e0 * inv;
            Sh[q * SROW + lane + 32] = e1 * inv;
        }
        CP_WAITG(0);
        __syncthreads();                               // S4: probs + V ready

        // ---- PV: lane = dim pair, V row read ONCE for 4 queries ----
        float o[4][2] = {};
        {
            const int slot0 = g0 ? 0 : 32;
            #pragma unroll
            for (int t = 0; t < 32; t++) {
                const float* vr = Ks + (krow0 + t) * KROW;
                const float vlo = vr[lane];
                const float vhi = vr[lane + 32];
                #pragma unroll
                for (int qq = 0; qq < 4; qq++) {
                    const int q = g0 ? (grp * 4 + qq) : (qq * 4 + grp);
                    const float pt = Sh[q * SROW + slot0 + t];
                    o[qq][0] += pt * vlo;
                    o[qq][1] += pt * vhi;
                }
            }
        }
        __syncthreads();                               // S5: probs + V reads done

        // ---- combine partial outputs in Sh (oex over probs region) ----
        if (g0) {
            #pragma unroll
            for (int qq = 0; qq < 4; qq++) {
                const int q = grp * 4 + qq;
                Sh[q * SROW + lane]      = o[qq][0];
                Sh[q * SROW + lane + 32] = o[qq][1];
            }
        }
        __syncthreads();                               // S6: g0 partials visible
        if (!g0) {
            #pragma unroll
            for (int qq = 0; qq < 4; qq++) {
                const int q = qq * 4 + grp;
                Sh[q * SROW + lane]      += o[qq][0];
                Sh[q * SROW + lane + 32] += o[qq][1];
            }
        }
        __syncthreads();                               // S7: sums visible

        // ---- output: warp w -> queries 2w, 2w+1; fused [hi|lo|hi] write ----
        #pragma unroll
        for (int qq = 0; qq < 2; qq++) {
            const int q = wid * 2 + qq;
            const float o0 = Sh[q * SROW + lane];
            const float o1 = Sh[q * SROW + lane + 32];
            const int n = (p << 10) + (i0 + (q >> 2)) * 32 + (j0 + (q & 3));
            const size_t ab = (size_t)(b * NN + n) * KK + h * DD;
            const __nv_bfloat16 h0 = __float2bfloat16(o0);
            const __nv_bfloat16 l0 = __float2bfloat16(o0 - __bfloat162float(h0));
            const __nv_bfloat16 h1 = __float2bfloat16(o1);
            const __nv_bfloat16 l1 = __float2bfloat16(o1 - __bfloat162float(h1));
            Aout[ab + lane]             = h0;
            Aout[ab + 512 + lane]       = l0;
            Aout[ab + 1024 + lane]      = h0;
            Aout[ab + lane + 32]        = h1;
            Aout[ab + 512 + lane + 32]  = l1;
            Aout[ab + 1024 + lane + 32] = h1;
        }
        __syncthreads();                               // S8: Sh reads done
    }
}

// ---------------------------------------------------------------------------
// Host side
// ---------------------------------------------------------------------------
extern "C" void kernel_launch(void* const* d_in, const int* in_sizes, int n_in,
                              void* d_out, int out_size)
{
    const float* x  = (const float*)d_in[0];
    const float* Wq = (const float*)d_in[1];
    const float* Wk = (const float*)d_in[2];
    const float* Wv = (const float*)d_in[3];
    const float* Wp = (const float*)d_in[4];
    const float* bp = (const float*)d_in[5];
    float* out = (float*)d_out;

    __nv_bfloat16 *A, *Bq, *Bo;
    float *qkv;
    cudaGetSymbolAddress((void**)&A,   g_A);
    cudaGetSymbolAddress((void**)&Bq,  g_Bqkv);
    cudaGetSymbolAddress((void**)&Bo,  g_Bout);
    cudaGetSymbolAddress((void**)&qkv, g_qkv);

    constexpr int SMEM_G = STAGES * STAGEB;                          // 81920
    constexpr int SMEM_A = (256 * KROW + 16 * SROW) * 4 + 256 * 4;   // 74752
    static bool s_attr = false;
    if (!s_attr) {
        cudaFuncSetAttribute(gemm_hmma,  cudaFuncAttributeMaxDynamicSharedMemorySize, SMEM_G);
        cudaFuncSetAttribute(attn_tile,  cudaFuncAttributeMaxDynamicSharedMemorySize, SMEM_A);
        s_attr = true;
    }

    // 1) hi/lo splits
    split3_a<<<(MM * 128 + 255) / 256, 256>>>(x, A, MM);
    split3_w4<<<dim3((CC * 128 + 255) / 256, 4), 256>>>(Wq, Wk, Wv, Wp, Bq, Bo);

    // 2) fused QKV projection
    gemm_hmma<<<dim3(NQKV / 128, MM / 128), 256, SMEM_G>>>(A, Bq, qkv, NQKV, nullptr);

    // 3) tiled sparse attention, key-major warps (writes split A directly)
    attn_tile<<<NB * 3 * 64, 256, SMEM_A>>>(qkv, A);

    // 4) output projection with bias
    gemm_hmma<<<dim3(CC / 128, MM / 128), 256, SMEM_G>>>(A, Bo, out, CC, bp);
}

// round 11
// speedup vs baseline: 1.5077x; 1.0413x over previous
#include <cuda_runtime.h>
#include <cuda_bf16.h>
#include <cstdint>
#include <cstddef>

#define NB   2
#define NN   3072
#define CC   512
#define MM   (NB * NN)      // 6144
#define HH   8
#define DD   64
#define KK   1536           // split-K: A=[hi|lo|hi], B=[hi|hi|lo]
#define NQKV 1536

// ---------------------------------------------------------------------------
// Device scratch
// ---------------------------------------------------------------------------
__device__ __align__(1024) __nv_bfloat16 g_A[(size_t)MM * KK];      // split activations
__device__ __align__(1024) __nv_bfloat16 g_Bqkv[(size_t)NQKV * KK]; // [Wq;Wk;Wv] split
__device__ __align__(1024) __nv_bfloat16 g_Bout[(size_t)CC * KK];   // Wp split
__device__ __align__(16)   float g_qkv[(size_t)MM * NQKV];          // q|k|v fp32

// ---------------------------------------------------------------------------
// helpers
// ---------------------------------------------------------------------------
__device__ __forceinline__ uint32_t smem_u32(const void* p) {
    uint32_t a;
    asm("{ .reg .u64 t; cvta.to.shared.u64 t, %1; cvt.u32.u64 %0, t; }" : "=r"(a) : "l"(p));
    return a;
}

#define CP16(dst_u32, src_ptr) \
    asm volatile("cp.async.cg.shared.global [%0], [%1], 16;" :: "r"(dst_u32), "l"(src_ptr))
#define CP_COMMIT()  asm volatile("cp.async.commit_group;" ::: "memory")
#define CP_WAITG(n)  asm volatile("cp.async.wait_group %0;" :: "n"(n) : "memory")

#define LDSM_X4(r0, r1, r2, r3, addr) \
    asm volatile("ldmatrix.sync.aligned.m8n8.x4.shared.b16 {%0,%1,%2,%3}, [%4];" \
                 : "=r"(r0), "=r"(r1), "=r"(r2), "=r"(r3) : "r"(addr))

__device__ __forceinline__ void mma16816(float* c, const uint32_t* a, const uint32_t* b) {
    asm volatile(
        "mma.sync.aligned.m16n8k16.row.col.f32.bf16.bf16.f32 "
        "{%0,%1,%2,%3}, {%4,%5,%6,%7}, {%8,%9}, {%0,%1,%2,%3};"
        : "+f"(c[0]), "+f"(c[1]), "+f"(c[2]), "+f"(c[3])
        : "r"(a[0]), "r"(a[1]), "r"(a[2]), "r"(a[3]), "r"(b[0]), "r"(b[1]));
}

// ---------------------------------------------------------------------------
// Hi/lo splitters:  activations -> [hi|lo|hi], weights -> [hi|hi|lo]
// ---------------------------------------------------------------------------
__device__ __forceinline__ void split_core(const float* __restrict__ in, int idx,
                                           int& r, int& c, uint2& H, uint2& L)
{
    r = idx >> 7;
    c = (idx & 127) << 2;
    float4 v = *reinterpret_cast<const float4*>(in + (size_t)r * CC + c);
    float f[4] = {v.x, v.y, v.z, v.w};
    uint32_t h[2], l[2];
    #pragma unroll
    for (int i = 0; i < 2; i++) {
        __nv_bfloat16 h0 = __float2bfloat16(f[2*i]);
        __nv_bfloat16 h1 = __float2bfloat16(f[2*i + 1]);
        __nv_bfloat16 l0 = __float2bfloat16(f[2*i]     - __bfloat162float(h0));
        __nv_bfloat16 l1 = __float2bfloat16(f[2*i + 1] - __bfloat162float(h1));
        h[i] = (uint32_t)__bfloat16_as_ushort(h0) | ((uint32_t)__bfloat16_as_ushort(h1) << 16);
        l[i] = (uint32_t)__bfloat16_as_ushort(l0) | ((uint32_t)__bfloat16_as_ushort(l1) << 16);
    }
    H = make_uint2(h[0], h[1]);
    L = make_uint2(l[0], l[1]);
}

__global__ void split3_a(const float* __restrict__ in, __nv_bfloat16* __restrict__ out, int rows)
{
    int idx = blockIdx.x * 256 + threadIdx.x;
    if (idx >= rows * 128) return;
    int r, c; uint2 H, L;
    split_core(in, idx, r, c, H, L);
    size_t base = (size_t)r * KK;
    *reinterpret_cast<uint2*>(out + base + c)        = H;
    *reinterpret_cast<uint2*>(out + base + 512 + c)  = L;
    *reinterpret_cast<uint2*>(out + base + 1024 + c) = H;
}

__global__ void split3_w4(const float* __restrict__ Wq, const float* __restrict__ Wk,
                          const float* __restrict__ Wv, const float* __restrict__ Wp,
                          __nv_bfloat16* __restrict__ Bq, __nv_bfloat16* __restrict__ Bo)
{
    const int which = blockIdx.y;
    const float* src = (which == 0) ? Wq : (which == 1) ? Wk : (which == 2) ? Wv : Wp;
    __nv_bfloat16* dst = (which == 0) ? Bq
                       : (which == 1) ? Bq + (size_t)512 * KK
                       : (which == 2) ? Bq + (size_t)1024 * KK
                       : Bo;
    int idx = blockIdx.x * 256 + threadIdx.x;
    if (idx >= CC * 128) return;
    int r, c; uint2 H, L;
    split_core(src, idx, r, c, H, L);
    size_t base = (size_t)r * KK;
    *reinterpret_cast<uint2*>(dst + base + c)        = H;
    *reinterpret_cast<uint2*>(dst + base + 512 + c)  = H;
    *reinterpret_cast<uint2*>(dst + base + 1024 + c) = L;
}

// ---------------------------------------------------------------------------
// HMMA GEMM (unchanged): CTA 128x128, BK=32, 4-stage cp.async, ldmatrix.
// ---------------------------------------------------------------------------
#define BK      32
#define PAD     40
#define STAGES  4
#define TILEBF  (128 * PAD)
#define STAGEB  (2 * TILEBF * 2)
#define NKCH    (KK / BK)              // 48

__global__ void __launch_bounds__(256, 2)
gemm_hmma(const __nv_bfloat16* __restrict__ Ag,
          const __nv_bfloat16* __restrict__ Bg,
          float* __restrict__ C, int ldc, const float* __restrict__ bias)
{
    extern __shared__ __align__(16) char smem[];
    const uint32_t sbase = smem_u32(smem);

    const int tid  = threadIdx.x;
    const int wid  = tid >> 5;
    const int lane = tid & 31;
    const int g    = lane >> 2;
    const int tig  = lane & 3;

    const int bm = blockIdx.y * 128;
    const int bn = blockIdx.x * 128;
    const int wm = (wid & 1) * 64;
    const int wn = (wid >> 1) * 32;

    const int r0 = tid >> 1;
    const int c0 = (tid & 1) * 16;

    auto load_stage = [&](int kt, int s) {
        const uint32_t aoff = sbase + (uint32_t)(s * TILEBF + r0 * PAD + c0) * 2;
        const uint32_t boff = aoff + (uint32_t)(STAGES * TILEBF) * 2;
        const __nv_bfloat16* ap = Ag + (size_t)(bm + r0) * KK + kt * BK + c0;
        const __nv_bfloat16* bp = Bg + (size_t)(bn + r0) * KK + kt * BK + c0;
        CP16(aoff,      ap);
        CP16(aoff + 16, ap + 8);
        CP16(boff,      bp);
        CP16(boff + 16, bp + 8);
    };

    const uint32_t a_off = (uint32_t)((wm + (lane & 15)) * PAD + (lane >> 4) * 8) * 2;
    const uint32_t b_off = (uint32_t)((wn + (lane >> 4) * 8 + (lane & 7)) * PAD
                                      + ((lane >> 3) & 1) * 8) * 2;

    float acc[4][4][4] = {};

    load_stage(0, 0); CP_COMMIT();
    load_stage(1, 1); CP_COMMIT();
    load_stage(2, 2); CP_COMMIT();

    for (int kt = 0; kt < NKCH; kt++) {
        CP_WAITG(2);
        __syncthreads();

        const int nk = kt + STAGES - 1;
        if (nk < NKCH) load_stage(nk, nk & 3);
        CP_COMMIT();

        const uint32_t at = sbase + (uint32_t)((kt & 3) * TILEBF) * 2 + a_off;
        const uint32_t bt = sbase + (uint32_t)((STAGES + (kt & 3)) * TILEBF) * 2 + b_off;

        #pragma unroll
        for (int kk = 0; kk < BK; kk += 16) {
            uint32_t af[4][4], bf[4][2];
            #pragma unroll
            for (int mi = 0; mi < 4; mi++)
                LDSM_X4(af[mi][0], af[mi][1], af[mi][2], af[mi][3],
                        at + (uint32_t)(mi * 16 * PAD + kk) * 2);
            #pragma unroll
            for (int np = 0; np < 2; np++)
                LDSM_X4(bf[2*np][0], bf[2*np][1], bf[2*np+1][0], bf[2*np+1][1],
                        bt + (uint32_t)(np * 16 * PAD + kk) * 2);
            #pragma unroll
            for (int mi = 0; mi < 4; mi++)
                #pragma unroll
                for (int ni = 0; ni < 4; ni++)
                    mma16816(acc[mi][ni], af[mi], bf[ni]);
        }
        __syncthreads();
    }

    #pragma unroll
    for (int mi = 0; mi < 4; mi++) {
        const int row0 = bm + wm + mi * 16 + g;
        #pragma unroll
        for (int ni = 0; ni < 4; ni++) {
            const int col = bn + wn + ni * 8 + tig * 2;
            float b0 = 0.f, b1 = 0.f;
            if (bias) { b0 = bias[col]; b1 = bias[col + 1]; }
            float2 lo = make_float2(acc[mi][ni][0] + b0, acc[mi][ni][1] + b1);
            float2 hi = make_float2(acc[mi][ni][2] + b0, acc[mi][ni][3] + b1);
            *reinterpret_cast<float2*>(C + (size_t)row0 * ldc + col)       = lo;
            *reinterpret_cast<float2*>(C + (size_t)(row0 + 8) * ldc + col) = hi;
        }
    }
}

// ---------------------------------------------------------------------------
// Tiled sparse triplane attention, key-major warps, V-from-L2 + K prefetch.
// Block = (b, p, 4x4 query tile); 256-key union.
// - K staged in smem (QK needs lane=key access, global would be uncoalesced).
// - V read DIRECTLY from global in PV (lane=dim -> coalesced; each V row
//   touched by exactly one warp). No V staging at all.
// - K(h+1) prefetches into the dead K buffer right after QK's sync,
//   overlapping softmax+PV+output.
// - dims handled as (2*lane, 2*lane+1) pairs: LDG.64 V loads, float2
//   combines, bf16x2 output stores.
// smem ~73KB -> 3 CTAs/SM.
// ---------------------------------------------------------------------------
#define KROW 68         // K buffer row stride (floats)
#define SROW 64         // shared-region row stride (floats)

__global__ void __launch_bounds__(256, 3)
attn_tile(const float* __restrict__ qkv, __nv_bfloat16* __restrict__ Aout)
{
    extern __shared__ __align__(16) float sm[];
    float* Ks    = sm;                         // [256][KROW]  K only
    float* Sh    = sm + 256 * KROW;            // [16][SROW]   Qh/scores/probs/oex
    int*   growS = (int*)(Sh + 16 * SROW);     // [256]
    const uint32_t ks_base = smem_u32(Ks);
    const uint32_t sh_base = smem_u32(Sh);

    const int x  = blockIdx.x;                 // 0..383
    const int b  = x / 192;
    const int r0 = x % 192;
    const int p  = r0 >> 6;
    const int t0 = r0 & 63;
    const int i0 = (t0 >> 3) << 2;
    const int j0 = (t0 & 7) << 2;

    const int tid  = threadIdx.x;
    const int wid  = tid >> 5;
    const int lane = tid & 31;

    const float* Bq = qkv + (size_t)b * NN * NQKV;

    // key-union row table (once)
    {
        const int rr = tid;
        const int rl = rr & 127;
        int gr;
        if (p == 0)
            gr = (rr < 128) ? (1024 + 32 * i0 + rl) : (2048 + 32 * j0 + rl);
        else if (p == 1)
            gr = (rr < 128) ? (32 * i0 + rl)
                            : (2048 + 32 * (rl & 31) + j0 + (rl >> 5));
        else
            gr = (rr < 128) ? (32 * (rl & 31) + i0 + (rl >> 5))
                            : (1024 + 32 * (rl & 31) + j0 + (rl >> 5));
        growS[rr] = gr;
    }
    __syncthreads();

    const bool g0    = (wid < 4);
    const int  grp   = g0 ? wid : (wid - 4);   // di (g0) or dj (g1)
    const int  krow0 = g0 ? (grp * 32) : (128 + grp * 32);
    const int  c4t   = tid & 15;
    const int  myGrow = growS[krow0 + lane];   // this warp's V rows (lane t)

    auto load_K = [&](int h) {
        #pragma unroll
        for (int it = 0; it < 16; it++) {
            const int rr = it * 16 + (tid >> 4);
            const float* src = Bq + (size_t)growS[rr] * NQKV + 512 + h * DD + c4t * 4;
            CP16(ks_base + (uint32_t)(rr * KROW + c4t * 4) * 4, src);
        }
    };

    load_K(0); CP_COMMIT();

    for (int h = 0; h < HH; h++) {
        // ---- Q(h) into Sh (over last head's oex; safe after S8) ----
        {
            const int qr = tid >> 4;
            const int n  = (p << 10) + (i0 + (qr >> 2)) * 32 + (j0 + (qr & 3));
            CP16(sh_base + (uint32_t)(qr * SROW + c4t * 4) * 4,
                 Bq + (size_t)n * NQKV + h * DD + c4t * 4);
        }
        CP_COMMIT(); CP_WAITG(0);
        __syncthreads();                               // S1: K(h) + Q(h) ready

        // ---- QK: lane = key, 4 queries per warp, K row read ONCE ----
        float s[4] = {0.f, 0.f, 0.f, 0.f};
        {
            const float4* Krow = reinterpret_cast<const float4*>(Ks + (krow0 + lane) * KROW);
            #pragma unroll
            for (int d4 = 0; d4 < 16; d4++) {
                const float4 kv = Krow[d4];
                #pragma unroll
                for (int qq = 0; qq < 4; qq++) {
                    const int q = g0 ? (grp * 4 + qq) : (qq * 4 + grp);
                    const float4 qv = *reinterpret_cast<const float4*>(Sh + q * SROW + d4 * 4);
                    s[qq] += qv.x * kv.x + qv.y * kv.y + qv.z * kv.z + qv.w * kv.w;
                }
            }
        }
        __syncthreads();                               // S2: K + Qh reads done

        // ---- prefetch K(h+1) into the dead K buffer ----
        if (h + 1 < HH) load_K(h + 1);
        CP_COMMIT();

        // ---- write scores over Qh ----
        {
            const int slot = g0 ? lane : (32 + lane);
            #pragma unroll
            for (int qq = 0; qq < 4; qq++) {
                const int q = g0 ? (grp * 4 + qq) : (qq * 4 + grp);
                Sh[q * SROW + slot] = s[qq] * 0.125f;
            }
        }
        __syncthreads();                               // S3: scores visible

        // ---- softmax in place: warp w -> queries 2w, 2w+1 ----
        #pragma unroll
        for (int qq = 0; qq < 2; qq++) {
            const int q = wid * 2 + qq;
            float s0 = Sh[q * SROW + lane];
            float s1 = Sh[q * SROW + lane + 32];
            float m = fmaxf(s0, s1);
            #pragma unroll
            for (int off = 16; off; off >>= 1)
                m = fmaxf(m, __shfl_xor_sync(0xffffffffu, m, off));
            const float e0 = __expf(s0 - m), e1 = __expf(s1 - m);
            float su = e0 + e1;
            #pragma unroll
            for (int off = 16; off; off >>= 1)
                su += __shfl_xor_sync(0xffffffffu, su, off);
            const float inv = 1.0f / su;
            Sh[q * SROW + lane]      = e0 * inv;
            Sh[q * SROW + lane + 32] = e1 * inv;
        }
        __syncthreads();                               // S4: probs visible

        // ---- PV: V straight from L2; lane = dim pair; V row read ONCE ----
        float o[4][2] = {};
        {
            const int slot0 = g0 ? 0 : 32;
            #pragma unroll
            for (int t = 0; t < 32; t++) {
                const int gr = __shfl_sync(0xffffffffu, myGrow, t);
                const float2 v2 = *reinterpret_cast<const float2*>(
                    Bq + (size_t)gr * NQKV + 1024 + h * DD + 2 * lane);
                #pragma unroll
                for (int qq = 0; qq < 4; qq++) {
                    const int q = g0 ? (grp * 4 + qq) : (qq * 4 + grp);
                    const float pt = Sh[q * SROW + slot0 + t];
                    o[qq][0] += pt * v2.x;
                    o[qq][1] += pt * v2.y;
                }
            }
        }
        __syncthreads();                               // S5: probs reads done

        // ---- combine partial outputs in Sh (float2 per lane) ----
        if (g0) {
            #pragma unroll
            for (int qq = 0; qq < 4; qq++) {
                const int q = grp * 4 + qq;
                *reinterpret_cast<float2*>(Sh + q * SROW + 2 * lane) =
                    make_float2(o[qq][0], o[qq][1]);
            }
        }
        __syncthreads();                               // S6: g0 partials visible
        if (!g0) {
            #pragma unroll
            for (int qq = 0; qq < 4; qq++) {
                const int q = qq * 4 + grp;
                float2 v = *reinterpret_cast<float2*>(Sh + q * SROW + 2 * lane);
                v.x += o[qq][0]; v.y += o[qq][1];
                *reinterpret_cast<float2*>(Sh + q * SROW + 2 * lane) = v;
            }
        }
        __syncthreads();                               // S7: sums visible

        // ---- output: warp w -> queries 2w, 2w+1; bf16x2 [hi|lo|hi] ----
        #pragma unroll
        for (int qq = 0; qq < 2; qq++) {
            const int q = wid * 2 + qq;
            const float2 ov = *reinterpret_cast<const float2*>(Sh + q * SROW + 2 * lane);
            const int n = (p << 10) + (i0 + (q >> 2)) * 32 + (j0 + (q & 3));
            const size_t ab = (size_t)(b * NN + n) * KK + h * DD;
            const __nv_bfloat16 h0 = __float2bfloat16(ov.x);
            const __nv_bfloat16 l0 = __float2bfloat16(ov.x - __bfloat162float(h0));
            const __nv_bfloat16 h1 = __float2bfloat16(ov.y);
            const __nv_bfloat16 l1 = __float2bfloat16(ov.y - __bfloat162float(h1));
            __nv_bfloat162 Hp; Hp.x = h0; Hp.y = h1;
            __nv_bfloat162 Lp; Lp.x = l0; Lp.y = l1;
            *reinterpret_cast<__nv_bfloat162*>(&Aout[ab + 2 * lane])        = Hp;
            *reinterpret_cast<__nv_bfloat162*>(&Aout[ab + 512 + 2 * lane])  = Lp;
            *reinterpret_cast<__nv_bfloat162*>(&Aout[ab + 1024 + 2 * lane]) = Hp;
        }
        __syncthreads();                               // S8: Sh reads done
    }
}

// ---------------------------------------------------------------------------
// Host side
// ---------------------------------------------------------------------------
extern "C" void kernel_launch(void* const* d_in, const int* in_sizes, int n_in,
                              void* d_out, int out_size)
{
    const float* x  = (const float*)d_in[0];
    const float* Wq = (const float*)d_in[1];
    const float* Wk = (const float*)d_in[2];
    const float* Wv = (const float*)d_in[3];
    const float* Wp = (const float*)d_in[4];
    const float* bp = (const float*)d_in[5];
    float* out = (float*)d_out;

    __nv_bfloat16 *A, *Bq, *Bo;
    float *qkv;
    cudaGetSymbolAddress((void**)&A,   g_A);
    cudaGetSymbolAddress((void**)&Bq,  g_Bqkv);
    cudaGetSymbolAddress((void**)&Bo,  g_Bout);
    cudaGetSymbolAddress((void**)&qkv, g_qkv);

    constexpr int SMEM_G = STAGES * STAGEB;                          // 81920
    constexpr int SMEM_A = (256 * KROW + 16 * SROW) * 4 + 256 * 4;   // 74752
    static bool s_attr = false;
    if (!s_attr) {
        cudaFuncSetAttribute(gemm_hmma,  cudaFuncAttributeMaxDynamicSharedMemorySize, SMEM_G);
        cudaFuncSetAttribute(attn_tile,  cudaFuncAttributeMaxDynamicSharedMemorySize, SMEM_A);
        s_attr = true;
    }

    // 1) hi/lo splits
    split3_a<<<(MM * 128 + 255) / 256, 256>>>(x, A, MM);
    split3_w4<<<dim3((CC * 128 + 255) / 256, 4), 256>>>(Wq, Wk, Wv, Wp, Bq, Bo);

    // 2) fused QKV projection
    gemm_hmma<<<dim3(NQKV / 128, MM / 128), 256, SMEM_G>>>(A, Bq, qkv, NQKV, nullptr);

    // 3) tiled sparse attention (V from L2, K prefetch, writes split A)
    attn_tile<<<NB * 3 * 64, 256, SMEM_A>>>(qkv, A);

    // 4) output projection with bias
    gemm_hmma<<<dim3(CC / 128, MM / 128), 256, SMEM_G>>>(A, Bo, out, CC, bp);
}

// round 12
// speedup vs baseline: 1.5877x; 1.0530x over previous
#include <cuda_runtime.h>
#include <cuda_bf16.h>
#include <cstdint>
#include <cstddef>

#define NB   2
#define NN   3072
#define CC   512
#define MM   (NB * NN)      // 6144
#define HH   8
#define DD   64
#define KK   1536           // split-K: A=[hi|lo|hi], B=[hi|hi|lo]
#define NQKV 1536

// ---------------------------------------------------------------------------
// Device scratch
// ---------------------------------------------------------------------------
__device__ __align__(1024) __nv_bfloat16 g_A[(size_t)MM * KK];      // split activations
__device__ __align__(1024) __nv_bfloat16 g_Bqkv[(size_t)NQKV * KK]; // [Wq;Wk;Wv] split
__device__ __align__(1024) __nv_bfloat16 g_Bout[(size_t)CC * KK];   // Wp split
__device__ __align__(16)   float g_qkv[(size_t)MM * NQKV];          // q|k|v fp32

// ---------------------------------------------------------------------------
// helpers
// ---------------------------------------------------------------------------
__device__ __forceinline__ uint32_t smem_u32(const void* p) {
    uint32_t a;
    asm("{ .reg .u64 t; cvta.to.shared.u64 t, %1; cvt.u32.u64 %0, t; }" : "=r"(a) : "l"(p));
    return a;
}

#define CP16(dst_u32, src_ptr) \
    asm volatile("cp.async.cg.shared.global [%0], [%1], 16;" :: "r"(dst_u32), "l"(src_ptr))
#define CP_COMMIT()  asm volatile("cp.async.commit_group;" ::: "memory")
#define CP_WAITG(n)  asm volatile("cp.async.wait_group %0;" :: "n"(n) : "memory")

#define LDSM_X4(r0, r1, r2, r3, addr) \
    asm volatile("ldmatrix.sync.aligned.m8n8.x4.shared.b16 {%0,%1,%2,%3}, [%4];" \
                 : "=r"(r0), "=r"(r1), "=r"(r2), "=r"(r3) : "r"(addr))

__device__ __forceinline__ void mma16816(float* c, const uint32_t* a, const uint32_t* b) {
    asm volatile(
        "mma.sync.aligned.m16n8k16.row.col.f32.bf16.bf16.f32 "
        "{%0,%1,%2,%3}, {%4,%5,%6,%7}, {%8,%9}, {%0,%1,%2,%3};"
        : "+f"(c[0]), "+f"(c[1]), "+f"(c[2]), "+f"(c[3])
        : "r"(a[0]), "r"(a[1]), "r"(a[2]), "r"(a[3]), "r"(b[0]), "r"(b[1]));
}

// ---------------------------------------------------------------------------
// Hi/lo splitters:  activations -> [hi|lo|hi], weights -> [hi|hi|lo]
// ---------------------------------------------------------------------------
__device__ __forceinline__ void split_core(const float* __restrict__ in, int idx,
                                           int& r, int& c, uint2& H, uint2& L)
{
    r = idx >> 7;
    c = (idx & 127) << 2;
    float4 v = *reinterpret_cast<const float4*>(in + (size_t)r * CC + c);
    float f[4] = {v.x, v.y, v.z, v.w};
    uint32_t h[2], l[2];
    #pragma unroll
    for (int i = 0; i < 2; i++) {
        __nv_bfloat16 h0 = __float2bfloat16(f[2*i]);
        __nv_bfloat16 h1 = __float2bfloat16(f[2*i + 1]);
        __nv_bfloat16 l0 = __float2bfloat16(f[2*i]     - __bfloat162float(h0));
        __nv_bfloat16 l1 = __float2bfloat16(f[2*i + 1] - __bfloat162float(h1));
        h[i] = (uint32_t)__bfloat16_as_ushort(h0) | ((uint32_t)__bfloat16_as_ushort(h1) << 16);
        l[i] = (uint32_t)__bfloat16_as_ushort(l0) | ((uint32_t)__bfloat16_as_ushort(l1) << 16);
    }
    H = make_uint2(h[0], h[1]);
    L = make_uint2(l[0], l[1]);
}

__global__ void split3_a(const float* __restrict__ in, __nv_bfloat16* __restrict__ out, int rows)
{
    int idx = blockIdx.x * 256 + threadIdx.x;
    if (idx >= rows * 128) return;
    int r, c; uint2 H, L;
    split_core(in, idx, r, c, H, L);
    size_t base = (size_t)r * KK;
    *reinterpret_cast<uint2*>(out + base + c)        = H;
    *reinterpret_cast<uint2*>(out + base + 512 + c)  = L;
    *reinterpret_cast<uint2*>(out + base + 1024 + c) = H;
}

__global__ void split3_w4(const float* __restrict__ Wq, const float* __restrict__ Wk,
                          const float* __restrict__ Wv, const float* __restrict__ Wp,
                          __nv_bfloat16* __restrict__ Bq, __nv_bfloat16* __restrict__ Bo)
{
    const int which = blockIdx.y;
    const float* src = (which == 0) ? Wq : (which == 1) ? Wk : (which == 2) ? Wv : Wp;
    __nv_bfloat16* dst = (which == 0) ? Bq
                       : (which == 1) ? Bq + (size_t)512 * KK
                       : (which == 2) ? Bq + (size_t)1024 * KK
                       : Bo;
    int idx = blockIdx.x * 256 + threadIdx.x;
    if (idx >= CC * 128) return;
    int r, c; uint2 H, L;
    split_core(src, idx, r, c, H, L);
    size_t base = (size_t)r * KK;
    *reinterpret_cast<uint2*>(dst + base + c)        = H;
    *reinterpret_cast<uint2*>(dst + base + 512 + c)  = H;
    *reinterpret_cast<uint2*>(dst + base + 1024 + c) = L;
}

// ---------------------------------------------------------------------------
// HMMA GEMM, templated on M-tile.  BM=128: 2 CTAs/SM (QKV proj, full chip at
// grid 576).  BM=64: 3 CTAs/SM (out proj: grid 384 = ONE full wave instead of
// 0.65 waves at BM=128).  BK=32, 4-stage cp.async, ldmatrix, ONE barrier per
// mainloop iteration (stage written at kt aliases kt-1, whose readers all
// passed the top barrier).
// ---------------------------------------------------------------------------
#define BK      32
#define PAD     40
#define STAGES  4
#define NKCH    (KK / BK)              // 48

template<int BM>
__global__ void __launch_bounds__(256, BM == 128 ? 2 : 3)
gemm_hmma(const __nv_bfloat16* __restrict__ Ag,
          const __nv_bfloat16* __restrict__ Bg,
          float* __restrict__ C, int ldc, const float* __restrict__ bias)
{
    constexpr int MI      = BM / 32;          // 4 (BM=128) or 2 (BM=64)
    constexpr int TILEA   = BM * PAD;         // bf16 per A tile
    constexpr int TILEB   = 128 * PAD;        // bf16 per B tile

    extern __shared__ __align__(16) char smem[];
    const uint32_t sbase = smem_u32(smem);

    const int tid  = threadIdx.x;
    const int wid  = tid >> 5;
    const int lane = tid & 31;
    const int g    = lane >> 2;
    const int tig  = lane & 3;

    const int bm = blockIdx.y * BM;
    const int bn = blockIdx.x * 128;
    const int wm = (wid & 1) * (BM / 2);
    const int wn = (wid >> 1) * 32;

    auto load_stage = [&](int kt, int s) {
        const uint32_t abase = sbase + (uint32_t)(s * TILEA) * 2;
        const uint32_t bbase = sbase + (uint32_t)(STAGES * TILEA + s * TILEB) * 2;
        if constexpr (BM == 128) {
            const int r0 = tid >> 1;
            const int c0 = (tid & 1) * 16;
            const __nv_bfloat16* ap = Ag + (size_t)(bm + r0) * KK + kt * BK + c0;
            const uint32_t aoff = abase + (uint32_t)(r0 * PAD + c0) * 2;
            CP16(aoff,      ap);
            CP16(aoff + 16, ap + 8);
        } else {
            const int r0 = tid >> 2;
            const int c0 = (tid & 3) * 8;
            const __nv_bfloat16* ap = Ag + (size_t)(bm + r0) * KK + kt * BK + c0;
            CP16(abase + (uint32_t)(r0 * PAD + c0) * 2, ap);
        }
        {
            const int r0 = tid >> 1;
            const int c0 = (tid & 1) * 16;
            const __nv_bfloat16* bp = Bg + (size_t)(bn + r0) * KK + kt * BK + c0;
            const uint32_t boff = bbase + (uint32_t)(r0 * PAD + c0) * 2;
            CP16(boff,      bp);
            CP16(boff + 16, bp + 8);
        }
    };

    const uint32_t a_off = (uint32_t)((wm + (lane & 15)) * PAD + (lane >> 4) * 8) * 2;
    const uint32_t b_off = (uint32_t)((wn + (lane >> 4) * 8 + (lane & 7)) * PAD
                                      + ((lane >> 3) & 1) * 8) * 2;

    float acc[MI][4][4] = {};

    load_stage(0, 0); CP_COMMIT();
    load_stage(1, 1); CP_COMMIT();
    load_stage(2, 2); CP_COMMIT();

    for (int kt = 0; kt < NKCH; kt++) {
        CP_WAITG(2);
        __syncthreads();   // stage kt visible; all warps done with kt-1 compute

        const int nk = kt + STAGES - 1;
        if (nk < NKCH) load_stage(nk, nk & 3);
        CP_COMMIT();

        const uint32_t at = sbase + (uint32_t)((kt & 3) * TILEA) * 2 + a_off;
        const uint32_t bt = sbase + (uint32_t)(STAGES * TILEA + (kt & 3) * TILEB) * 2 + b_off;

        #pragma unroll
        for (int kk = 0; kk < BK; kk += 16) {
            uint32_t af[MI][4], bf[4][2];
            #pragma unroll
            for (int mi = 0; mi < MI; mi++)
                LDSM_X4(af[mi][0], af[mi][1], af[mi][2], af[mi][3],
                        at + (uint32_t)(mi * 16 * PAD + kk) * 2);
            #pragma unroll
            for (int np = 0; np < 2; np++)
                LDSM_X4(bf[2*np][0], bf[2*np][1], bf[2*np+1][0], bf[2*np+1][1],
                        bt + (uint32_t)(np * 16 * PAD + kk) * 2);
            #pragma unroll
            for (int mi = 0; mi < MI; mi++)
                #pragma unroll
                for (int ni = 0; ni < 4; ni++)
                    mma16816(acc[mi][ni], af[mi], bf[ni]);
        }
    }

    #pragma unroll
    for (int mi = 0; mi < MI; mi++) {
        const int row0 = bm + wm + mi * 16 + g;
        #pragma unroll
        for (int ni = 0; ni < 4; ni++) {
            const int col = bn + wn + ni * 8 + tig * 2;
            float b0 = 0.f, b1 = 0.f;
            if (bias) { b0 = bias[col]; b1 = bias[col + 1]; }
            float2 lo = make_float2(acc[mi][ni][0] + b0, acc[mi][ni][1] + b1);
            float2 hi = make_float2(acc[mi][ni][2] + b0, acc[mi][ni][3] + b1);
            *reinterpret_cast<float2*>(C + (size_t)row0 * ldc + col)       = lo;
            *reinterpret_cast<float2*>(C + (size_t)(row0 + 8) * ldc + col) = hi;
        }
    }
}

// ---------------------------------------------------------------------------
// Tiled sparse triplane attention (unchanged from R11): key-major warps,
// V-from-L2, K prefetch, fused [hi|lo|hi] output split.  3 CTAs/SM.
// ---------------------------------------------------------------------------
#define KROW 68         // K buffer row stride (floats)
#define SROW 64         // shared-region row stride (floats)

__global__ void __launch_bounds__(256, 3)
attn_tile(const float* __restrict__ qkv, __nv_bfloat16* __restrict__ Aout)
{
    extern __shared__ __align__(16) float sm[];
    float* Ks    = sm;                         // [256][KROW]  K only
    float* Sh    = sm + 256 * KROW;            // [16][SROW]   Qh/scores/probs/oex
    int*   growS = (int*)(Sh + 16 * SROW);     // [256]
    const uint32_t ks_base = smem_u32(Ks);
    const uint32_t sh_base = smem_u32(Sh);

    const int x  = blockIdx.x;                 // 0..383
    const int b  = x / 192;
    const int r0 = x % 192;
    const int p  = r0 >> 6;
    const int t0 = r0 & 63;
    const int i0 = (t0 >> 3) << 2;
    const int j0 = (t0 & 7) << 2;

    const int tid  = threadIdx.x;
    const int wid  = tid >> 5;
    const int lane = tid & 31;

    const float* Bq = qkv + (size_t)b * NN * NQKV;

    {
        const int rr = tid;
        const int rl = rr & 127;
        int gr;
        if (p == 0)
            gr = (rr < 128) ? (1024 + 32 * i0 + rl) : (2048 + 32 * j0 + rl);
        else if (p == 1)
            gr = (rr < 128) ? (32 * i0 + rl)
                            : (2048 + 32 * (rl & 31) + j0 + (rl >> 5));
        else
            gr = (rr < 128) ? (32 * (rl & 31) + i0 + (rl >> 5))
                            : (1024 + 32 * (rl & 31) + j0 + (rl >> 5));
        growS[rr] = gr;
    }
    __syncthreads();

    const bool g0     = (wid < 4);
    const int  grp    = g0 ? wid : (wid - 4);
    const int  krow0  = g0 ? (grp * 32) : (128 + grp * 32);
    const int  c4t    = tid & 15;
    const int  myGrow = growS[krow0 + lane];

    auto load_K = [&](int h) {
        #pragma unroll
        for (int it = 0; it < 16; it++) {
            const int rr = it * 16 + (tid >> 4);
            const float* src = Bq + (size_t)growS[rr] * NQKV + 512 + h * DD + c4t * 4;
            CP16(ks_base + (uint32_t)(rr * KROW + c4t * 4) * 4, src);
        }
    };

    load_K(0); CP_COMMIT();

    for (int h = 0; h < HH; h++) {
        {
            const int qr = tid >> 4;
            const int n  = (p << 10) + (i0 + (qr >> 2)) * 32 + (j0 + (qr & 3));
            CP16(sh_base + (uint32_t)(qr * SROW + c4t * 4) * 4,
                 Bq + (size_t)n * NQKV + h * DD + c4t * 4);
        }
        CP_COMMIT(); CP_WAITG(0);
        __syncthreads();                               // S1

        float s[4] = {0.f, 0.f, 0.f, 0.f};
        {
            const float4* Krow = reinterpret_cast<const float4*>(Ks + (krow0 + lane) * KROW);
            #pragma unroll
            for (int d4 = 0; d4 < 16; d4++) {
                const float4 kv = Krow[d4];
                #pragma unroll
                for (int qq = 0; qq < 4; qq++) {
                    const int q = g0 ? (grp * 4 + qq) : (qq * 4 + grp);
                    const float4 qv = *reinterpret_cast<const float4*>(Sh + q * SROW + d4 * 4);
                    s[qq] += qv.x * kv.x + qv.y * kv.y + qv.z * kv.z + qv.w * kv.w;
                }
            }
        }
        __syncthreads();                               // S2

        if (h + 1 < HH) load_K(h + 1);
        CP_COMMIT();

        {
            const int slot = g0 ? lane : (32 + lane);
            #pragma unroll
            for (int qq = 0; qq < 4; qq++) {
                const int q = g0 ? (grp * 4 + qq) : (qq * 4 + grp);
                Sh[q * SROW + slot] = s[qq] * 0.125f;
            }
        }
        __syncthreads();                               // S3

        #pragma unroll
        for (int qq = 0; qq < 2; qq++) {
            const int q = wid * 2 + qq;
            float s0 = Sh[q * SROW + lane];
            float s1 = Sh[q * SROW + lane + 32];
            float m = fmaxf(s0, s1);
            #pragma unroll
            for (int off = 16; off; off >>= 1)
                m = fmaxf(m, __shfl_xor_sync(0xffffffffu, m, off));
            const float e0 = __expf(s0 - m), e1 = __expf(s1 - m);
            float su = e0 + e1;
            #pragma unroll
            for (int off = 16; off; off >>= 1)
                su += __shfl_xor_sync(0xffffffffu, su, off);
            const float inv = 1.0f / su;
            Sh[q * SROW + lane]      = e0 * inv;
            Sh[q * SROW + lane + 32] = e1 * inv;
        }
        __syncthreads();                               // S4

        float o[4][2] = {};
        {
            const int slot0 = g0 ? 0 : 32;
            #pragma unroll
            for (int t = 0; t < 32; t++) {
                const int gr = __shfl_sync(0xffffffffu, myGrow, t);
                const float2 v2 = *reinterpret_cast<const float2*>(
                    Bq + (size_t)gr * NQKV + 1024 + h * DD + 2 * lane);
                #pragma unroll
                for (int qq = 0; qq < 4; qq++) {
                    const int q = g0 ? (grp * 4 + qq) : (qq * 4 + grp);
                    const float pt = Sh[q * SROW + slot0 + t];
                    o[qq][0] += pt * v2.x;
                    o[qq][1] += pt * v2.y;
                }
            }
        }
        __syncthreads();                               // S5

        if (g0) {
            #pragma unroll
            for (int qq = 0; qq < 4; qq++) {
                const int q = grp * 4 + qq;
                *reinterpret_cast<float2*>(Sh + q * SROW + 2 * lane) =
                    make_float2(o[qq][0], o[qq][1]);
            }
        }
        __syncthreads();                               // S6
        if (!g0) {
            #pragma unroll
            for (int qq = 0; qq < 4; qq++) {
                const int q = qq * 4 + grp;
                float2 v = *reinterpret_cast<float2*>(Sh + q * SROW + 2 * lane);
                v.x += o[qq][0]; v.y += o[qq][1];
                *reinterpret_cast<float2*>(Sh + q * SROW + 2 * lane) = v;
            }
        }
        __syncthreads();                               // S7

        #pragma unroll
        for (int qq = 0; qq < 2; qq++) {
            const int q = wid * 2 + qq;
            const float2 ov = *reinterpret_cast<const float2*>(Sh + q * SROW + 2 * lane);
            const int n = (p << 10) + (i0 + (q >> 2)) * 32 + (j0 + (q & 3));
            const size_t ab = (size_t)(b * NN + n) * KK + h * DD;
            const __nv_bfloat16 h0 = __float2bfloat16(ov.x);
            const __nv_bfloat16 l0 = __float2bfloat16(ov.x - __bfloat162float(h0));
            const __nv_bfloat16 h1 = __float2bfloat16(ov.y);
            const __nv_bfloat16 l1 = __float2bfloat16(ov.y - __bfloat162float(h1));
            __nv_bfloat162 Hp; Hp.x = h0; Hp.y = h1;
            __nv_bfloat162 Lp; Lp.x = l0; Lp.y = l1;
            *reinterpret_cast<__nv_bfloat162*>(&Aout[ab + 2 * lane])        = Hp;
            *reinterpret_cast<__nv_bfloat162*>(&Aout[ab + 512 + 2 * lane])  = Lp;
            *reinterpret_cast<__nv_bfloat162*>(&Aout[ab + 1024 + 2 * lane]) = Hp;
        }
        __syncthreads();                               // S8
    }
}

// ---------------------------------------------------------------------------
// Host side
// ---------------------------------------------------------------------------
extern "C" void kernel_launch(void* const* d_in, const int* in_sizes, int n_in,
                              void* d_out, int out_size)
{
    const float* x  = (const float*)d_in[0];
    const float* Wq = (const float*)d_in[1];
    const float* Wk = (const float*)d_in[2];
    const float* Wv = (const float*)d_in[3];
    const float* Wp = (const float*)d_in[4];
    const float* bp = (const float*)d_in[5];
    float* out = (float*)d_out;

    __nv_bfloat16 *A, *Bq, *Bo;
    float *qkv;
    cudaGetSymbolAddress((void**)&A,   g_A);
    cudaGetSymbolAddress((void**)&Bq,  g_Bqkv);
    cudaGetSymbolAddress((void**)&Bo,  g_Bout);
    cudaGetSymbolAddress((void**)&qkv, g_qkv);

    constexpr int SMEM_G128 = STAGES * (128 + 128) * PAD * 2;        // 81920
    constexpr int SMEM_G64  = STAGES * (64 + 128) * PAD * 2;         // 61440
    constexpr int SMEM_A    = (256 * KROW + 16 * SROW) * 4 + 256 * 4; // 74752
    static bool s_attr = false;
    if (!s_attr) {
        cudaFuncSetAttribute(gemm_hmma<128>, cudaFuncAttributeMaxDynamicSharedMemorySize, SMEM_G128);
        cudaFuncSetAttribute(gemm_hmma<64>,  cudaFuncAttributeMaxDynamicSharedMemorySize, SMEM_G64);
        cudaFuncSetAttribute(attn_tile,      cudaFuncAttributeMaxDynamicSharedMemorySize, SMEM_A);
        s_attr = true;
    }

    // 1) hi/lo splits
    split3_a<<<(MM * 128 + 255) / 256, 256>>>(x, A, MM);
    split3_w4<<<dim3((CC * 128 + 255) / 256, 4), 256>>>(Wq, Wk, Wv, Wp, Bq, Bo);

    // 2) fused QKV projection (BM=128, 2 full waves)
    gemm_hmma<128><<<dim3(NQKV / 128, MM / 128), 256, SMEM_G128>>>(A, Bq, qkv, NQKV, nullptr);

    // 3) tiled sparse attention (V from L2, K prefetch, writes split A)
    attn_tile<<<NB * 3 * 64, 256, SMEM_A>>>(qkv, A);

    // 4) output projection (BM=64: 384 CTAs, 3/SM -> one full wave)
    gemm_hmma<64><<<dim3(CC / 128, MM / 64), 256, SMEM_G64>>>(A, Bo, out, CC, bp);
}